// round 3
// baseline (speedup 1.0000x reference)
#include <cuda_runtime.h>

// Problem constants
#define BB   8
#define NN   4096
#define NPTS 1024          // NP
#define NS   32
#define CF   64
#define C0   67            // 3 + CF
#define O1   64
#define O2   128
#define O3   256
#define MTOT (BB*NPTS*NS)  // 262144 spatial columns
#define BPTOT (BB*NPTS)    // 8192 (b,p) groups
#define BNEPS 1e-5f

// ---------------- scratch (device globals: no allocation allowed) ----------------
__device__ __align__(16) float g_ptsT[BB*NN*CF];     // points transposed (B,N,CF)  8.4MB
__device__ __align__(16) float g_x1[O1*MTOT];        // layer1 raw output           67MB
__device__ __align__(16) float g_x2[O2*MTOT];        // layer2 raw output           134MB
__device__ __align__(16) float g_xmax[O3*BPTOT];     // layer3 raw, maxed over NS   8.4MB
__device__ __align__(16) float g_xmin[O3*BPTOT];     // layer3 raw, min over NS     8.4MB
__device__ float g_statS[3*256*64];                  // per-layer per-channel slotted sums
__device__ float g_statQ[3*256*64];                  // slotted sum of squares
__device__ float g_bnA[3*256];                       // BN affine: a = gamma*rsqrt(var+eps)
__device__ float g_bnC[3*256];                       // BN affine: c = beta - a*mu

// ---------------- zero the stat accumulators (graph-replay safe) ----------------
__global__ void zero_stats() {
    int i = blockIdx.x * blockDim.x + threadIdx.x;
    if (i < 3*256*64) { g_statS[i] = 0.f; g_statQ[i] = 0.f; }
}

// ---------------- transpose points (B,CF,N) -> (B,N,CF) ----------------
__global__ void transpose_pts(const float* __restrict__ pts) {
    __shared__ float tile[32][33];
    int b  = blockIdx.z;
    int n0 = blockIdx.x * 32, c0 = blockIdx.y * 32;
    int tx = threadIdx.x, ty = threadIdx.y;   // 32 x 8
    #pragma unroll
    for (int i = 0; i < 32; i += 8)
        tile[ty + i][tx] = pts[(size_t)b*CF*NN + (size_t)(c0 + ty + i)*NN + n0 + tx];
    __syncthreads();
    #pragma unroll
    for (int i = 0; i < 32; i += 8)
        g_ptsT[((size_t)b*NN + n0 + ty + i)*CF + c0 + tx] = tile[tx][ty + i];
}

// ---------------- kernel A: gather + layer1 conv + stats + new_xyz ----------------
// one block per (b,p); 256 threads = 8 warps; warp w computes outputs [8w,8w+8) for all 32 s
__global__ __launch_bounds__(256) void gather_conv1(
    const float* __restrict__ xyz, const int* __restrict__ sample_idx,
    const int* __restrict__ neighbor_idx, const float* __restrict__ W0,
    const float* __restrict__ b0, float* __restrict__ out, int xyz_ofs)
{
    int bp = blockIdx.x;
    int b = bp >> 10;
    __shared__ __align__(16) float x0s[C0][33];
    __shared__ __align__(16) float W0s[C0][O1];
    __shared__ float b0s[O1];
    __shared__ int   sidx[NS];
    __shared__ float ctr[3];

    int t = threadIdx.x;
    if (t < NS) sidx[t] = neighbor_idx[bp*NS + t];
    if (t == 0) {
        int sp = sample_idx[bp];
        #pragma unroll
        for (int k = 0; k < 3; k++) {
            float v = xyz[((size_t)b*NN + sp)*3 + k];
            ctr[k] = v;
            if (xyz_ofs > 0) out[bp*3 + k] = v;    // new_xyz part of output
        }
    }
    // stage W0 transposed: W0s[c][o] = W0[o*67+c]
    for (int e = t; e < C0*O1; e += 256) {
        int o = e & 63, c = e >> 6;
        W0s[c][o] = W0[o*C0 + c];
    }
    if (t < O1) b0s[t] = b0[t];
    __syncthreads();

    int w = t >> 5, lane = t & 31;
    // gather: warp w handles s = 4w..4w+3; 8 lanes per s
    {
        int s = 4*w + (lane >> 3);
        int li = lane & 7;
        int idx = sidx[s];
        if (li < 3) x0s[li][s] = xyz[((size_t)b*NN + idx)*3 + li] - ctr[li];
        const float* prow = &g_ptsT[((size_t)b*NN + idx)*CF];
        #pragma unroll
        for (int c = li; c < CF; c += 8) x0s[3 + c][s] = prow[c];
    }
    __syncthreads();

    // GEMM: o0 = 8w, column = lane
    int o0 = w * 8;
    float acc[8];
    #pragma unroll
    for (int i = 0; i < 8; i++) acc[i] = b0s[o0 + i];
    #pragma unroll
    for (int c = 0; c < C0; c++) {
        float xv = x0s[c][lane];
        float4 wa = *(const float4*)&W0s[c][o0];
        float4 wb = *(const float4*)&W0s[c][o0 + 4];
        acc[0] = fmaf(wa.x, xv, acc[0]);
        acc[1] = fmaf(wa.y, xv, acc[1]);
        acc[2] = fmaf(wa.z, xv, acc[2]);
        acc[3] = fmaf(wa.w, xv, acc[3]);
        acc[4] = fmaf(wb.x, xv, acc[4]);
        acc[5] = fmaf(wb.y, xv, acc[5]);
        acc[6] = fmaf(wb.z, xv, acc[6]);
        acc[7] = fmaf(wb.w, xv, acc[7]);
    }
    int m = bp*NS + lane;
    #pragma unroll
    for (int i = 0; i < 8; i++) g_x1[(size_t)(o0 + i)*MTOT + m] = acc[i];
    // stats: per-o reduce over 32 lanes (s), slot atomics
    #pragma unroll
    for (int i = 0; i < 8; i++) {
        float s1 = acc[i], s2 = acc[i]*acc[i];
        #pragma unroll
        for (int d = 16; d; d >>= 1) {
            s1 += __shfl_xor_sync(0xffffffffu, s1, d);
            s2 += __shfl_xor_sync(0xffffffffu, s2, d);
        }
        if (lane == 0) {
            int slot = (o0 + i)*64 + (bp & 63);
            atomicAdd(&g_statS[slot], s1);
            atomicAdd(&g_statQ[slot], s2);
        }
    }
}

// ---------------- BN finalize: a,c per channel ----------------
__global__ void bn_finalize(int layer, int O, const float* __restrict__ gamma,
                            const float* __restrict__ beta)
{
    int o = blockIdx.x * blockDim.x + threadIdx.x;
    if (o >= O) return;
    float s = 0.f, q = 0.f;
    int base = layer*256*64 + o*64;
    #pragma unroll 8
    for (int k = 0; k < 64; k++) { s += g_statS[base + k]; q += g_statQ[base + k]; }
    float invM = 1.0f / (float)MTOT;
    float mu   = s * invM;
    float var  = q * invM - mu*mu;
    float a    = gamma[o] * rsqrtf(var + BNEPS);
    g_bnA[layer*256 + o] = a;
    g_bnC[layer*256 + o] = beta[o] - a*mu;
}

// ---------------- conv layers 2/3: 64x64 block tile, 4x4 thread tile ----------------
// LAYER==2: C=64,O=128, in=g_x1 (+BN0/ReLU), out=g_x2 raw + stats1
// LAYER==3: C=128,O=256, in=g_x2 (+BN1/ReLU), out = max/min over NS + stats2
template <int LAYER>
__global__ __launch_bounds__(256) void conv_kernel(const float* __restrict__ W,
                                                   const float* __restrict__ bias)
{
    constexpr int C     = (LAYER == 2) ? O1 : O2;
    constexpr int FINAL = (LAYER == 3);
    constexpr int bnofs = (LAYER == 2) ? 0 : 256;
    constexpr int stofs = (LAYER == 2) ? 1*256*64 : 2*256*64;
    const float* __restrict__ Xin = (LAYER == 2) ? g_x1 : g_x2;

    __shared__ __align__(16) float Xs[64][64];
    __shared__ __align__(16) float Ws[64][64];

    int t  = threadIdx.x;
    int tx = t & 15, ty = t >> 4;
    int m0 = blockIdx.x * 64;
    int o0 = blockIdx.y * 64;

    float acc[4][4];
    #pragma unroll
    for (int oi = 0; oi < 4; oi++) {
        float bv = bias[o0 + ty*4 + oi];
        #pragma unroll
        for (int mi = 0; mi < 4; mi++) acc[oi][mi] = bv;
    }

    for (int kc0 = 0; kc0 < C; kc0 += 64) {
        // stage X tile with fused BN(prev)+ReLU, float4 coalesced
        #pragma unroll
        for (int r = 0; r < 4; r++) {
            int idx = t + r*256;
            int c   = idx >> 4;
            int col = (idx & 15) << 2;
            float4 v = *(const float4*)&Xin[(size_t)(kc0 + c)*MTOT + m0 + col];
            float a = g_bnA[bnofs + kc0 + c];
            float cc = g_bnC[bnofs + kc0 + c];
            v.x = fmaxf(fmaf(a, v.x, cc), 0.f);
            v.y = fmaxf(fmaf(a, v.y, cc), 0.f);
            v.z = fmaxf(fmaf(a, v.z, cc), 0.f);
            v.w = fmaxf(fmaf(a, v.w, cc), 0.f);
            *(float4*)&Xs[c][col] = v;
        }
        // stage W tile transposed: Ws[c][o] = W[(o0+o)*C + kc0+c]
        #pragma unroll
        for (int r = 0; r < 16; r++) {
            int idx = t + (r << 8);
            int o = idx & 63, c = idx >> 6;
            Ws[c][o] = W[(o0 + o)*C + kc0 + c];
        }
        __syncthreads();
        #pragma unroll 16
        for (int c = 0; c < 64; c++) {
            float4 xv = *(const float4*)&Xs[c][tx << 2];
            float4 wv = *(const float4*)&Ws[c][ty << 2];
            acc[0][0] = fmaf(wv.x, xv.x, acc[0][0]);
            acc[0][1] = fmaf(wv.x, xv.y, acc[0][1]);
            acc[0][2] = fmaf(wv.x, xv.z, acc[0][2]);
            acc[0][3] = fmaf(wv.x, xv.w, acc[0][3]);
            acc[1][0] = fmaf(wv.y, xv.x, acc[1][0]);
            acc[1][1] = fmaf(wv.y, xv.y, acc[1][1]);
            acc[1][2] = fmaf(wv.y, xv.z, acc[1][2]);
            acc[1][3] = fmaf(wv.y, xv.w, acc[1][3]);
            acc[2][0] = fmaf(wv.z, xv.x, acc[2][0]);
            acc[2][1] = fmaf(wv.z, xv.y, acc[2][1]);
            acc[2][2] = fmaf(wv.z, xv.z, acc[2][2]);
            acc[2][3] = fmaf(wv.z, xv.w, acc[2][3]);
            acc[3][0] = fmaf(wv.w, xv.x, acc[3][0]);
            acc[3][1] = fmaf(wv.w, xv.y, acc[3][1]);
            acc[3][2] = fmaf(wv.w, xv.z, acc[3][2]);
            acc[3][3] = fmaf(wv.w, xv.w, acc[3][3]);
        }
        __syncthreads();
    }

    int mbase = m0 + (tx << 2);
    if (!FINAL) {
        #pragma unroll
        for (int oi = 0; oi < 4; oi++) {
            float4 st = make_float4(acc[oi][0], acc[oi][1], acc[oi][2], acc[oi][3]);
            *(float4*)&g_x2[(size_t)(o0 + ty*4 + oi)*MTOT + mbase] = st;
        }
    }
    // stats: reduce over the 16 tx threads (lane bits 0..3) per o
    #pragma unroll
    for (int oi = 0; oi < 4; oi++) {
        float s1 = acc[oi][0] + acc[oi][1] + acc[oi][2] + acc[oi][3];
        float s2 = acc[oi][0]*acc[oi][0] + acc[oi][1]*acc[oi][1]
                 + acc[oi][2]*acc[oi][2] + acc[oi][3]*acc[oi][3];
        #pragma unroll
        for (int d = 8; d; d >>= 1) {
            s1 += __shfl_xor_sync(0xffffffffu, s1, d);
            s2 += __shfl_xor_sync(0xffffffffu, s2, d);
        }
        if (tx == 0) {
            int slot = stofs + (o0 + ty*4 + oi)*64 + (blockIdx.x & 63);
            atomicAdd(&g_statS[slot], s1);
            atomicAdd(&g_statQ[slot], s2);
        }
    }
    if (FINAL) {
        // max/min over each NS=32 group; group = 8 tx threads (lane bits 0..2)
        #pragma unroll
        for (int oi = 0; oi < 4; oi++) {
            float mx = fmaxf(fmaxf(acc[oi][0], acc[oi][1]), fmaxf(acc[oi][2], acc[oi][3]));
            float mn = fminf(fminf(acc[oi][0], acc[oi][1]), fminf(acc[oi][2], acc[oi][3]));
            #pragma unroll
            for (int d = 4; d; d >>= 1) {
                mx = fmaxf(mx, __shfl_xor_sync(0xffffffffu, mx, d));
                mn = fminf(mn, __shfl_xor_sync(0xffffffffu, mn, d));
            }
            if ((tx & 7) == 0) {
                int bp = (m0 >> 5) + (tx >> 3);
                g_xmax[(o0 + ty*4 + oi)*BPTOT + bp] = mx;
                g_xmin[(o0 + ty*4 + oi)*BPTOT + bp] = mn;
            }
        }
    }
}

// ---------------- final: apply BN3 affine + ReLU to maxed values, write output ----------------
__global__ void finalize_out(float* __restrict__ out, int ofs) {
    int idx = blockIdx.x * blockDim.x + threadIdx.x;   // idx = o*8192 + bp
    int o  = idx >> 13;
    int bp = idx & 8191;
    float a = g_bnA[2*256 + o];
    float c = g_bnC[2*256 + o];
    float x = (a >= 0.f) ? g_xmax[idx] : g_xmin[idx];  // max commutes with monotone affine
    float y = fmaxf(fmaf(a, x, c), 0.f);
    int b = bp >> 10, p = bp & 1023;
    out[ofs + ((size_t)b*O3 + o)*NPTS + p] = y;
}

// ---------------- launch ----------------
extern "C" void kernel_launch(void* const* d_in, const int* in_sizes, int n_in,
                              void* d_out, int out_size) {
    const float* xyz    = (const float*)d_in[0];
    const float* points = (const float*)d_in[1];
    const int*   sidx   = (const int*)  d_in[2];
    const int*   nidx   = (const int*)  d_in[3];
    const float* W0 = (const float*)d_in[4],  *b0 = (const float*)d_in[5];
    const float* g0 = (const float*)d_in[6],  *be0 = (const float*)d_in[7];
    const float* W1 = (const float*)d_in[8],  *b1 = (const float*)d_in[9];
    const float* g1 = (const float*)d_in[10], *be1 = (const float*)d_in[11];
    const float* W2 = (const float*)d_in[12], *b2 = (const float*)d_in[13];
    const float* g2 = (const float*)d_in[14], *be2 = (const float*)d_in[15];
    float* out = (float*)d_out;

    int xyz_ofs = (out_size > O3*BPTOT) ? (out_size - O3*BPTOT) : 0;  // new_xyz prefix size

    zero_stats<<<(3*256*64 + 255)/256, 256>>>();
    transpose_pts<<<dim3(NN/32, CF/32, BB), dim3(32, 8)>>>(points);
    gather_conv1<<<BPTOT, 256>>>(xyz, sidx, nidx, W0, b0, out, xyz_ofs);
    bn_finalize<<<1, 64>>>(0, O1, g0, be0);
    conv_kernel<2><<<dim3(MTOT/64, O2/64), 256>>>(W1, b1);
    bn_finalize<<<1, 128>>>(1, O2, g1, be1);
    conv_kernel<3><<<dim3(MTOT/64, O3/64), 256>>>(W2, b2);
    bn_finalize<<<1, 256>>>(2, O3, g2, be2);
    finalize_out<<<(O3*BPTOT)/256, 256>>>(out, xyz_ofs);
}

// round 8
// speedup vs baseline: 3.0001x; 3.0001x over previous
#include <cuda_runtime.h>
#include <cuda_bf16.h>

// Problem constants
#define BB   8
#define NN   4096
#define NPTS 1024
#define NS   32
#define CF   64
#define C0   67
#define O1   64
#define O2   128
#define O3   256
#define MTOT (BB*NPTS*NS)  // 262144
#define BPTOT (BB*NPTS)    // 8192
#define BNEPS 1e-5f

// ---------------- scratch (device globals; no allocation allowed) ----------------
__device__ __align__(16) float g_ptsT[BB*NN*CF];          // (B,N,CF)
__device__ __align__(16) float g_x1m[(size_t)MTOT*O1];    // layer1 raw, m-major [m][64]
__device__ __align__(16) float g_x2m[(size_t)MTOT*O2];    // layer2 raw, m-major [m][128]
__device__ __align__(16) float g_xmaxT[BPTOT*O3];         // [bp][256]
__device__ __align__(16) float g_xminT[BPTOT*O3];         // [bp][256]
__device__ __align__(16) float g_statS[3*256*64];
__device__ __align__(16) float g_statQ[3*256*64];
__device__ __align__(16) float g_bnA[3*256];
__device__ __align__(16) float g_bnC[3*256];
__device__ __align__(16) __nv_bfloat16 g_W1h[O2*O1], g_W1l[O2*O1];   // [o][c]
__device__ __align__(16) __nv_bfloat16 g_W2h[O3*O2], g_W2l[O3*O2];   // [o][c]

// ---------------- helpers (plain sm_80-class PTX only) ----------------
static __device__ __forceinline__ unsigned smem_u32(const void* p) {
    unsigned a;
    asm("{ .reg .u64 t; cvta.to.shared.u64 t, %1; cvt.u32.u64 %0, t; }" : "=r"(a) : "l"(p));
    return a;
}
static __device__ __forceinline__ void ldsm4(unsigned* r, unsigned addr) {
    asm volatile("ldmatrix.sync.aligned.m8n8.x4.shared.b16 {%0,%1,%2,%3}, [%4];"
        : "=r"(r[0]), "=r"(r[1]), "=r"(r[2]), "=r"(r[3]) : "r"(addr));
}
static __device__ __forceinline__ void mma16816(float* d, const unsigned* a,
                                                unsigned b0, unsigned b1) {
    asm volatile("mma.sync.aligned.m16n8k16.row.col.f32.bf16.bf16.f32 "
        "{%0,%1,%2,%3}, {%4,%5,%6,%7}, {%8,%9}, {%0,%1,%2,%3};"
        : "+f"(d[0]), "+f"(d[1]), "+f"(d[2]), "+f"(d[3])
        : "r"(a[0]), "r"(a[1]), "r"(a[2]), "r"(a[3]), "r"(b0), "r"(b1));
}
static __device__ __forceinline__ unsigned bfpack(__nv_bfloat16 a, __nv_bfloat16 b) {
    unsigned short ua = *(unsigned short*)&a, ub = *(unsigned short*)&b;
    return (unsigned)ua | ((unsigned)ub << 16);
}
static __device__ __forceinline__ void split_bf16(float x, __nv_bfloat16& h, __nv_bfloat16& l) {
    h = __float2bfloat16_rn(x);
    l = __float2bfloat16_rn(x - __bfloat162float(h));
}
static __device__ __forceinline__ float rsum3(float v) {
    v += __shfl_xor_sync(0xffffffffu, v, 4);
    v += __shfl_xor_sync(0xffffffffu, v, 8);
    v += __shfl_xor_sync(0xffffffffu, v, 16);
    return v;
}
static __device__ __forceinline__ float rmax3(float v) {
    v = fmaxf(v, __shfl_xor_sync(0xffffffffu, v, 4));
    v = fmaxf(v, __shfl_xor_sync(0xffffffffu, v, 8));
    v = fmaxf(v, __shfl_xor_sync(0xffffffffu, v, 16));
    return v;
}
static __device__ __forceinline__ float rmin3(float v) {
    v = fminf(v, __shfl_xor_sync(0xffffffffu, v, 4));
    v = fminf(v, __shfl_xor_sync(0xffffffffu, v, 8));
    v = fminf(v, __shfl_xor_sync(0xffffffffu, v, 16));
    return v;
}

// ---------------- utility kernels ----------------
__global__ void zero_stats() {
    int i = blockIdx.x * blockDim.x + threadIdx.x;
    if (i < 3*256*64) { g_statS[i] = 0.f; g_statQ[i] = 0.f; }
}

__global__ void transpose_pts(const float* __restrict__ pts) {
    __shared__ float tile[32][33];
    int b  = blockIdx.z;
    int n0 = blockIdx.x * 32, c0 = blockIdx.y * 32;
    int tx = threadIdx.x, ty = threadIdx.y;
    #pragma unroll
    for (int i = 0; i < 32; i += 8)
        tile[ty + i][tx] = pts[(size_t)b*CF*NN + (size_t)(c0 + ty + i)*NN + n0 + tx];
    __syncthreads();
    #pragma unroll
    for (int i = 0; i < 32; i += 8)
        g_ptsT[((size_t)b*NN + n0 + ty + i)*CF + c0 + tx] = tile[tx][ty + i];
}

__global__ void convert_w(const float* __restrict__ W1, const float* __restrict__ W2) {
    int t = blockIdx.x * 256 + threadIdx.x;
    if (t < O2*O1) {
        __nv_bfloat16 h, l; split_bf16(W1[t], h, l);
        g_W1h[t] = h; g_W1l[t] = l;
    }
    if (t < O3*O2) {
        __nv_bfloat16 h, l; split_bf16(W2[t], h, l);
        g_W2h[t] = h; g_W2l[t] = l;
    }
}

// ---------------- layer 1: gather + conv (FFMA) ----------------
__global__ __launch_bounds__(256) void gather_conv1(
    const float* __restrict__ xyz, const int* __restrict__ sample_idx,
    const int* __restrict__ neighbor_idx, const float* __restrict__ W0,
    const float* __restrict__ b0, float* __restrict__ out, int xyz_ofs)
{
    int bp = blockIdx.x;
    int b = bp >> 10;
    __shared__ __align__(16) float x0s[C0][33];
    __shared__ __align__(16) float W0s[C0][O1];
    __shared__ float b0s[O1];
    __shared__ int   sidx[NS];
    __shared__ float ctr[3];

    int t = threadIdx.x;
    if (t < NS) sidx[t] = neighbor_idx[bp*NS + t];
    if (t == 0) {
        int sp = sample_idx[bp];
        #pragma unroll
        for (int k = 0; k < 3; k++) {
            float v = xyz[((size_t)b*NN + sp)*3 + k];
            ctr[k] = v;
            if (xyz_ofs > 0) out[bp*3 + k] = v;
        }
    }
    for (int e = t; e < C0*O1; e += 256) {
        int o = e & 63, c = e >> 6;
        W0s[c][o] = W0[o*C0 + c];
    }
    if (t < O1) b0s[t] = b0[t];
    __syncthreads();

    int w = t >> 5, lane = t & 31;
    {
        int s = 4*w + (lane >> 3);
        int li = lane & 7;
        int idx = sidx[s];
        if (li < 3) x0s[li][s] = xyz[((size_t)b*NN + idx)*3 + li] - ctr[li];
        const float* prow = &g_ptsT[((size_t)b*NN + idx)*CF];
        #pragma unroll
        for (int c = li; c < CF; c += 8) x0s[3 + c][s] = prow[c];
    }
    __syncthreads();

    int o0 = w * 8;
    float acc[8];
    #pragma unroll
    for (int i = 0; i < 8; i++) acc[i] = b0s[o0 + i];
    #pragma unroll
    for (int c = 0; c < C0; c++) {
        float xv = x0s[c][lane];
        float4 wa = *(const float4*)&W0s[c][o0];
        float4 wb = *(const float4*)&W0s[c][o0 + 4];
        acc[0] = fmaf(wa.x, xv, acc[0]);
        acc[1] = fmaf(wa.y, xv, acc[1]);
        acc[2] = fmaf(wa.z, xv, acc[2]);
        acc[3] = fmaf(wa.w, xv, acc[3]);
        acc[4] = fmaf(wb.x, xv, acc[4]);
        acc[5] = fmaf(wb.y, xv, acc[5]);
        acc[6] = fmaf(wb.z, xv, acc[6]);
        acc[7] = fmaf(wb.w, xv, acc[7]);
    }
    int m = bp*NS + lane;
    *(float4*)&g_x1m[(size_t)m*O1 + o0]     = make_float4(acc[0], acc[1], acc[2], acc[3]);
    *(float4*)&g_x1m[(size_t)m*O1 + o0 + 4] = make_float4(acc[4], acc[5], acc[6], acc[7]);
    #pragma unroll
    for (int i = 0; i < 8; i++) {
        float s1 = acc[i], s2 = acc[i]*acc[i];
        #pragma unroll
        for (int d = 16; d; d >>= 1) {
            s1 += __shfl_xor_sync(0xffffffffu, s1, d);
            s2 += __shfl_xor_sync(0xffffffffu, s2, d);
        }
        if (lane == 0) {
            int slot = (o0 + i)*64 + (bp & 63);
            atomicAdd(&g_statS[slot], s1);
            atomicAdd(&g_statQ[slot], s2);
        }
    }
}

// ---------------- BN finalize ----------------
__global__ void bn_finalize(int layer, int O, const float* __restrict__ gamma,
                            const float* __restrict__ beta)
{
    int o = blockIdx.x * blockDim.x + threadIdx.x;
    if (o >= O) return;
    float s = 0.f, q = 0.f;
    int base = layer*256*64 + o*64;
    #pragma unroll 8
    for (int k = 0; k < 64; k++) { s += g_statS[base + k]; q += g_statQ[base + k]; }
    float invM = 1.0f / (float)MTOT;
    float mu   = s * invM;
    float var  = q * invM - mu*mu;
    float a    = gamma[o] * rsqrtf(var + BNEPS);
    g_bnA[layer*256 + o] = a;
    g_bnC[layer*256 + o] = beta[o] - a*mu;
}

// ---------------- layers 2/3: warp-MMA (mma.sync bf16, hi/lo 3-pass) ----------------
// CTA tile: 128m x 128o, K chunked by 64. 8 warps: warp = 32m x 64o.
// smem (dynamic, 73728B): Xh[128x72bf16 pad], Xl, Wh, Wl — each 18432B, row stride 144B.
#define SM_XH 0
#define SM_XL 18432
#define SM_WH 36864
#define SM_WL 55296
#define CONV_SMEM 73728

template <int LAYER>
__global__ __launch_bounds__(256, 2) void conv_mma(const float* __restrict__ bias)
{
    constexpr int C      = (LAYER == 2) ? O1 : O2;
    constexpr int NCHUNK = C / 64;
    constexpr int bnofs  = (LAYER == 2) ? 0 : 256;
    constexpr int stofs  = (LAYER == 2) ? 1*256*64 : 2*256*64;
    const float* __restrict__ Xin = (LAYER == 2) ? g_x1m : g_x2m;
    const unsigned* __restrict__ WhG =
        (const unsigned*)((LAYER == 2) ? (const void*)g_W1h : (const void*)g_W2h);
    const unsigned* __restrict__ WlG =
        (const unsigned*)((LAYER == 2) ? (const void*)g_W1l : (const void*)g_W2l);

    extern __shared__ __align__(16) char smc[];
    unsigned sb = smem_u32(smc);
    unsigned* Xhs = (unsigned*)(smc + SM_XH);
    unsigned* Xls = (unsigned*)(smc + SM_XL);
    unsigned* Whs = (unsigned*)(smc + SM_WH);
    unsigned* Wls = (unsigned*)(smc + SM_WL);

    int t = threadIdx.x, w = t >> 5, lane = t & 31;
    int m0 = blockIdx.x * 128;
    int o0 = blockIdx.y * 128;

    float acc[2][8][4];
    #pragma unroll
    for (int a = 0; a < 2; a++)
        #pragma unroll
        for (int b = 0; b < 8; b++)
            #pragma unroll
            for (int c = 0; c < 4; c++) acc[a][b][c] = 0.f;

    int mw = (w & 3) * 32;         // warp m offset within CTA tile
    int ow = (w >> 2) * 64;        // warp o offset within CTA tile
    // ldmatrix per-lane base addresses (byte offsets; stride 144B per row)
    unsigned aoff = sb + SM_XH + (unsigned)(mw + (lane & 15)) * 144u + ((lane & 16) ? 16u : 0u);
    unsigned boff = sb + SM_WH + (unsigned)(ow + ((lane >> 4) << 3) + (lane & 7)) * 144u
                    + ((lane & 8) ? 16u : 0u);

    for (int ck = 0; ck < NCHUNK; ck++) {
        int kc0 = ck * 64;
        // ---- stage X chunk: BN(prev)+ReLU + hi/lo split, padded rows ----
        #pragma unroll
        for (int idx = t; idx < 2048; idx += 256) {
            int row = idx >> 4, c4 = (idx & 15) << 2;
            float4 v  = *(const float4*)&Xin[(size_t)(m0 + row)*C + kc0 + c4];
            float4 A  = *(const float4*)&g_bnA[bnofs + kc0 + c4];
            float4 Cc = *(const float4*)&g_bnC[bnofs + kc0 + c4];
            float x0 = fmaxf(fmaf(A.x, v.x, Cc.x), 0.f);
            float x1 = fmaxf(fmaf(A.y, v.y, Cc.y), 0.f);
            float x2 = fmaxf(fmaf(A.z, v.z, Cc.z), 0.f);
            float x3 = fmaxf(fmaf(A.w, v.w, Cc.w), 0.f);
            __nv_bfloat16 h0,l0,h1,l1,h2,l2,h3,l3;
            split_bf16(x0,h0,l0); split_bf16(x1,h1,l1);
            split_bf16(x2,h2,l2); split_bf16(x3,h3,l3);
            uint2 hp; hp.x = bfpack(h0,h1); hp.y = bfpack(h2,h3);
            uint2 lp; lp.x = bfpack(l0,l1); lp.y = bfpack(l2,l3);
            *(uint2*)&Xhs[row*36 + (c4 >> 1)] = hp;
            *(uint2*)&Xls[row*36 + (c4 >> 1)] = lp;
        }
        // ---- stage W chunk (pre-split bf16), padded rows ----
        #pragma unroll
        for (int idx = t; idx < 1024; idx += 256) {
            int row = idx >> 3, cu = (idx & 7) << 2;
            size_t src = (size_t)(o0 + row)*(C/2) + (kc0 >> 1) + cu;
            *(uint4*)&Whs[row*36 + cu] = *(const uint4*)&WhG[src];
            *(uint4*)&Wls[row*36 + cu] = *(const uint4*)&WlG[src];
        }
        __syncthreads();

        // ---- compute: 4 k-steps of m16n8k16, hi/lo 3-pass ----
        #pragma unroll
        for (int kt = 0; kt < 4; kt++) {
            unsigned ab = aoff + kt*32;
            unsigned ah0[4], ah1[4], al0[4], al1[4];
            ldsm4(ah0, ab);
            ldsm4(ah1, ab + 16*144);
            ldsm4(al0, ab + SM_XL);
            ldsm4(al1, ab + SM_XL + 16*144);
            #pragma unroll
            for (int np = 0; np < 4; np++) {
                unsigned bb = boff + np*(16*144) + kt*32;
                unsigned bh[4], bl[4];
                ldsm4(bh, bb);
                ldsm4(bl, bb + (SM_WL - SM_WH));
                // n-tile 2np
                mma16816(acc[0][2*np],   ah0, bh[0], bh[1]);
                mma16816(acc[0][2*np],   ah0, bl[0], bl[1]);
                mma16816(acc[0][2*np],   al0, bh[0], bh[1]);
                mma16816(acc[1][2*np],   ah1, bh[0], bh[1]);
                mma16816(acc[1][2*np],   ah1, bl[0], bl[1]);
                mma16816(acc[1][2*np],   al1, bh[0], bh[1]);
                // n-tile 2np+1
                mma16816(acc[0][2*np+1], ah0, bh[2], bh[3]);
                mma16816(acc[0][2*np+1], ah0, bl[2], bl[3]);
                mma16816(acc[0][2*np+1], al0, bh[2], bh[3]);
                mma16816(acc[1][2*np+1], ah1, bh[2], bh[3]);
                mma16816(acc[1][2*np+1], ah1, bl[2], bl[3]);
                mma16816(acc[1][2*np+1], al1, bh[2], bh[3]);
            }
        }
        __syncthreads();
    }

    // ---- epilogue: bias, stats, store (L2) or max/min (L3) ----
    int g  = lane >> 2;
    int c2 = (lane & 3) << 1;
    int bslot = blockIdx.x & 63;
    #pragma unroll
    for (int nt = 0; nt < 8; nt++) {
        int col = o0 + ow + nt*8 + c2;          // global o for cols (col, col+1)
        float2 bv = *(const float2*)&bias[col];
        float v00 = acc[0][nt][0] + bv.x, v01 = acc[0][nt][1] + bv.y;
        float v10 = acc[0][nt][2] + bv.x, v11 = acc[0][nt][3] + bv.y;
        float w00 = acc[1][nt][0] + bv.x, w01 = acc[1][nt][1] + bv.y;
        float w10 = acc[1][nt][2] + bv.x, w11 = acc[1][nt][3] + bv.y;

        if (LAYER == 2) {
            int r = m0 + mw + g;
            *(float2*)&g_x2m[(size_t)(r     )*O2 + col] = make_float2(v00, v01);
            *(float2*)&g_x2m[(size_t)(r +  8)*O2 + col] = make_float2(v10, v11);
            *(float2*)&g_x2m[(size_t)(r + 16)*O2 + col] = make_float2(w00, w01);
            *(float2*)&g_x2m[(size_t)(r + 24)*O2 + col] = make_float2(w10, w11);
        }

        float s0 = rsum3(v00 + v10 + w00 + w10);
        float s1 = rsum3(v01 + v11 + w01 + w11);
        float q0 = rsum3(v00*v00 + v10*v10 + w00*w00 + w10*w10);
        float q1 = rsum3(v01*v01 + v11*v11 + w01*w01 + w11*w11);

        float mx0 = 0.f, mx1 = 0.f, mn0 = 0.f, mn1 = 0.f;
        if (LAYER == 3) {
            mx0 = rmax3(fmaxf(fmaxf(v00, v10), fmaxf(w00, w10)));
            mn0 = rmin3(fminf(fminf(v00, v10), fminf(w00, w10)));
            mx1 = rmax3(fmaxf(fmaxf(v01, v11), fmaxf(w01, w11)));
            mn1 = rmin3(fminf(fminf(v01, v11), fminf(w01, w11)));
        }
        if (lane < 4) {
            atomicAdd(&g_statS[stofs + (col    )*64 + bslot], s0);
            atomicAdd(&g_statS[stofs + (col + 1)*64 + bslot], s1);
            atomicAdd(&g_statQ[stofs + (col    )*64 + bslot], q0);
            atomicAdd(&g_statQ[stofs + (col + 1)*64 + bslot], q1);
            if (LAYER == 3) {
                int bp = (m0 + mw) >> 5;
                *(float2*)&g_xmaxT[bp*O3 + col] = make_float2(mx0, mx1);
                *(float2*)&g_xminT[bp*O3 + col] = make_float2(mn0, mn1);
            }
        }
    }
}

// ---------------- final: BN2 affine + ReLU on max/min, transpose to output ----------------
__global__ void finalize_out(float* __restrict__ out, int ofs) {
    __shared__ float tile[32][33];
    int o0  = blockIdx.y * 32;
    int bp0 = blockIdx.x * 32;
    int tx = threadIdx.x, ty = threadIdx.y;   // 32 x 8
    float a = g_bnA[512 + o0 + tx], c = g_bnC[512 + o0 + tx];
    #pragma unroll
    for (int i = 0; i < 32; i += 8) {
        int bp = bp0 + ty + i;
        float mx = g_xmaxT[bp*O3 + o0 + tx];
        float mn = g_xminT[bp*O3 + o0 + tx];
        float x = (a >= 0.f) ? mx : mn;
        tile[ty + i][tx] = fmaxf(fmaf(a, x, c), 0.f);
    }
    __syncthreads();
    int b  = bp0 >> 10;
    int p0 = bp0 & 1023;
    #pragma unroll
    for (int i = 0; i < 32; i += 8) {
        int o = o0 + ty + i;
        out[ofs + ((size_t)b*O3 + o)*NPTS + p0 + tx] = tile[tx][ty + i];
    }
}

// ---------------- launch ----------------
extern "C" void kernel_launch(void* const* d_in, const int* in_sizes, int n_in,
                              void* d_out, int out_size) {
    const float* xyz    = (const float*)d_in[0];
    const float* points = (const float*)d_in[1];
    const int*   sidx   = (const int*)  d_in[2];
    const int*   nidx   = (const int*)  d_in[3];
    const float* W0 = (const float*)d_in[4],  *b0 = (const float*)d_in[5];
    const float* g0 = (const float*)d_in[6],  *be0 = (const float*)d_in[7];
    const float* W1 = (const float*)d_in[8],  *b1 = (const float*)d_in[9];
    const float* g1 = (const float*)d_in[10], *be1 = (const float*)d_in[11];
    const float* W2 = (const float*)d_in[12], *b2 = (const float*)d_in[13];
    const float* g2 = (const float*)d_in[14], *be2 = (const float*)d_in[15];
    float* out = (float*)d_out;

    int xyz_ofs = (out_size > O3*BPTOT) ? (out_size - O3*BPTOT) : 0;

    cudaFuncSetAttribute(conv_mma<2>, cudaFuncAttributeMaxDynamicSharedMemorySize, CONV_SMEM);
    cudaFuncSetAttribute(conv_mma<3>, cudaFuncAttributeMaxDynamicSharedMemorySize, CONV_SMEM);

    zero_stats<<<(3*256*64 + 255)/256, 256>>>();
    transpose_pts<<<dim3(NN/32, CF/32, BB), dim3(32, 8)>>>(points);
    convert_w<<<(O3*O2 + 255)/256, 256>>>(W1, W2);
    gather_conv1<<<BPTOT, 256>>>(xyz, sidx, nidx, W0, b0, out, xyz_ofs);
    bn_finalize<<<1, 64>>>(0, O1, g0, be0);
    conv_mma<2><<<dim3(MTOT/128, 1), 256, CONV_SMEM>>>(b1);
    bn_finalize<<<1, 128>>>(1, O2, g1, be1);
    conv_mma<3><<<dim3(MTOT/128, O3/128), 256, CONV_SMEM>>>(b2);
    bn_finalize<<<1, 256>>>(2, O3, g2, be2);
    finalize_out<<<dim3(BPTOT/32, O3/32), dim3(32, 8)>>>(out, xyz_ofs);
}

// round 11
// speedup vs baseline: 3.0110x; 1.0036x over previous
#include <cuda_runtime.h>
#include <cuda_bf16.h>

// Problem constants
#define BB   8
#define NN   4096
#define NPTS 1024
#define NS   32
#define CF   64
#define C0   67
#define O1   64
#define O2   128
#define O3   256
#define MTOT (BB*NPTS*NS)  // 262144
#define BPTOT (BB*NPTS)    // 8192
#define BNEPS 1e-5f

// ---------------- scratch (device globals; no allocation allowed) ----------------
__device__ __align__(16) float g_ptsT[BB*NN*CF];          // (B,N,CF)
__device__ __align__(16) float g_x1m[(size_t)MTOT*O1];    // layer1 raw, m-major [m][64]
__device__ __align__(16) float g_x2m[(size_t)MTOT*O2];    // layer2 raw, m-major [m][128]
__device__ __align__(16) float g_xmaxT[BPTOT*O3];         // [bp][256]
__device__ __align__(16) float g_xminT[BPTOT*O3];         // [bp][256]
__device__ __align__(16) float g_statS[3*256*64];
__device__ __align__(16) float g_statQ[3*256*64];
__device__ __align__(16) float g_bnA[3*256];
__device__ __align__(16) float g_bnC[3*256];
__device__ __align__(16) __nv_bfloat16 g_W1h[O2*O1], g_W1l[O2*O1];   // [o][c]
__device__ __align__(16) __nv_bfloat16 g_W2h[O3*O2], g_W2l[O3*O2];   // [o][c]

// ---------------- helpers (plain sm_80-class PTX only) ----------------
static __device__ __forceinline__ unsigned smem_u32(const void* p) {
    unsigned a;
    asm("{ .reg .u64 t; cvta.to.shared.u64 t, %1; cvt.u32.u64 %0, t; }" : "=r"(a) : "l"(p));
    return a;
}
static __device__ __forceinline__ void ldsm4(unsigned* r, unsigned addr) {
    asm volatile("ldmatrix.sync.aligned.m8n8.x4.shared.b16 {%0,%1,%2,%3}, [%4];"
        : "=r"(r[0]), "=r"(r[1]), "=r"(r[2]), "=r"(r[3]) : "r"(addr));
}
static __device__ __forceinline__ void mma16816(float* d, const unsigned* a,
                                                unsigned b0, unsigned b1) {
    asm volatile("mma.sync.aligned.m16n8k16.row.col.f32.bf16.bf16.f32 "
        "{%0,%1,%2,%3}, {%4,%5,%6,%7}, {%8,%9}, {%0,%1,%2,%3};"
        : "+f"(d[0]), "+f"(d[1]), "+f"(d[2]), "+f"(d[3])
        : "r"(a[0]), "r"(a[1]), "r"(a[2]), "r"(a[3]), "r"(b0), "r"(b1));
}
static __device__ __forceinline__ unsigned bfpack(__nv_bfloat16 a, __nv_bfloat16 b) {
    unsigned short ua = *(unsigned short*)&a, ub = *(unsigned short*)&b;
    return (unsigned)ua | ((unsigned)ub << 16);
}
static __device__ __forceinline__ void split_bf16(float x, __nv_bfloat16& h, __nv_bfloat16& l) {
    h = __float2bfloat16_rn(x);
    l = __float2bfloat16_rn(x - __bfloat162float(h));
}
static __device__ __forceinline__ float rsum3(float v) {
    v += __shfl_xor_sync(0xffffffffu, v, 4);
    v += __shfl_xor_sync(0xffffffffu, v, 8);
    v += __shfl_xor_sync(0xffffffffu, v, 16);
    return v;
}
static __device__ __forceinline__ float rmax3(float v) {
    v = fmaxf(v, __shfl_xor_sync(0xffffffffu, v, 4));
    v = fmaxf(v, __shfl_xor_sync(0xffffffffu, v, 8));
    v = fmaxf(v, __shfl_xor_sync(0xffffffffu, v, 16));
    return v;
}
static __device__ __forceinline__ float rmin3(float v) {
    v = fminf(v, __shfl_xor_sync(0xffffffffu, v, 4));
    v = fminf(v, __shfl_xor_sync(0xffffffffu, v, 8));
    v = fminf(v, __shfl_xor_sync(0xffffffffu, v, 16));
    return v;
}

// ---------------- utility kernels ----------------
__global__ void zero_stats() {
    int i = blockIdx.x * blockDim.x + threadIdx.x;
    if (i < 3*256*64) { g_statS[i] = 0.f; g_statQ[i] = 0.f; }
}

__global__ void transpose_pts(const float* __restrict__ pts) {
    __shared__ float tile[32][33];
    int b  = blockIdx.z;
    int n0 = blockIdx.x * 32, c0 = blockIdx.y * 32;
    int tx = threadIdx.x, ty = threadIdx.y;
    #pragma unroll
    for (int i = 0; i < 32; i += 8)
        tile[ty + i][tx] = pts[(size_t)b*CF*NN + (size_t)(c0 + ty + i)*NN + n0 + tx];
    __syncthreads();
    #pragma unroll
    for (int i = 0; i < 32; i += 8)
        g_ptsT[((size_t)b*NN + n0 + ty + i)*CF + c0 + tx] = tile[tx][ty + i];
}

__global__ void convert_w(const float* __restrict__ W1, const float* __restrict__ W2) {
    int t = blockIdx.x * 256 + threadIdx.x;
    if (t < O2*O1) {
        __nv_bfloat16 h, l; split_bf16(W1[t], h, l);
        g_W1h[t] = h; g_W1l[t] = l;
    }
    if (t < O3*O2) {
        __nv_bfloat16 h, l; split_bf16(W2[t], h, l);
        g_W2h[t] = h; g_W2l[t] = l;
    }
}

// ---------------- layer 1: gather + conv (FFMA) ----------------
__global__ __launch_bounds__(256) void gather_conv1(
    const float* __restrict__ xyz, const int* __restrict__ sample_idx,
    const int* __restrict__ neighbor_idx, const float* __restrict__ W0,
    const float* __restrict__ b0, float* __restrict__ out, int xyz_ofs)
{
    int bp = blockIdx.x;
    int b = bp >> 10;
    __shared__ __align__(16) float x0s[C0][33];
    __shared__ __align__(16) float W0s[C0][O1];
    __shared__ float b0s[O1];
    __shared__ int   sidx[NS];
    __shared__ float ctr[3];

    int t = threadIdx.x;
    if (t < NS) sidx[t] = neighbor_idx[bp*NS + t];
    if (t == 0) {
        int sp = sample_idx[bp];
        #pragma unroll
        for (int k = 0; k < 3; k++) {
            float v = xyz[((size_t)b*NN + sp)*3 + k];
            ctr[k] = v;
            if (xyz_ofs > 0) out[bp*3 + k] = v;
        }
    }
    for (int e = t; e < C0*O1; e += 256) {
        int o = e & 63, c = e >> 6;
        W0s[c][o] = W0[o*C0 + c];
    }
    if (t < O1) b0s[t] = b0[t];
    __syncthreads();

    int w = t >> 5, lane = t & 31;
    {
        int s = 4*w + (lane >> 3);
        int li = lane & 7;
        int idx = sidx[s];
        if (li < 3) x0s[li][s] = xyz[((size_t)b*NN + idx)*3 + li] - ctr[li];
        const float* prow = &g_ptsT[((size_t)b*NN + idx)*CF];
        #pragma unroll
        for (int c = li; c < CF; c += 8) x0s[3 + c][s] = prow[c];
    }
    __syncthreads();

    int o0 = w * 8;
    float acc[8];
    #pragma unroll
    for (int i = 0; i < 8; i++) acc[i] = b0s[o0 + i];
    #pragma unroll
    for (int c = 0; c < C0; c++) {
        float xv = x0s[c][lane];
        float4 wa = *(const float4*)&W0s[c][o0];
        float4 wb = *(const float4*)&W0s[c][o0 + 4];
        acc[0] = fmaf(wa.x, xv, acc[0]);
        acc[1] = fmaf(wa.y, xv, acc[1]);
        acc[2] = fmaf(wa.z, xv, acc[2]);
        acc[3] = fmaf(wa.w, xv, acc[3]);
        acc[4] = fmaf(wb.x, xv, acc[4]);
        acc[5] = fmaf(wb.y, xv, acc[5]);
        acc[6] = fmaf(wb.z, xv, acc[6]);
        acc[7] = fmaf(wb.w, xv, acc[7]);
    }
    int m = bp*NS + lane;
    *(float4*)&g_x1m[(size_t)m*O1 + o0]     = make_float4(acc[0], acc[1], acc[2], acc[3]);
    *(float4*)&g_x1m[(size_t)m*O1 + o0 + 4] = make_float4(acc[4], acc[5], acc[6], acc[7]);
    #pragma unroll
    for (int i = 0; i < 8; i++) {
        float s1 = acc[i], s2 = acc[i]*acc[i];
        #pragma unroll
        for (int d = 16; d; d >>= 1) {
            s1 += __shfl_xor_sync(0xffffffffu, s1, d);
            s2 += __shfl_xor_sync(0xffffffffu, s2, d);
        }
        if (lane == 0) {
            int slot = (o0 + i)*64 + (bp & 63);
            atomicAdd(&g_statS[slot], s1);
            atomicAdd(&g_statQ[slot], s2);
        }
    }
}

// ---------------- BN finalize ----------------
__global__ void bn_finalize(int layer, int O, const float* __restrict__ gamma,
                            const float* __restrict__ beta)
{
    int o = blockIdx.x * blockDim.x + threadIdx.x;
    if (o >= O) return;
    float s = 0.f, q = 0.f;
    int base = layer*256*64 + o*64;
    #pragma unroll 8
    for (int k = 0; k < 64; k++) { s += g_statS[base + k]; q += g_statQ[base + k]; }
    float invM = 1.0f / (float)MTOT;
    float mu   = s * invM;
    float var  = q * invM - mu*mu;
    float a    = gamma[o] * rsqrtf(var + BNEPS);
    g_bnA[layer*256 + o] = a;
    g_bnC[layer*256 + o] = beta[o] - a*mu;
}

// ---------------- layers 2/3: warp-MMA (mma.sync bf16, hi/lo 3-pass) ----------------
// CTA tile: 128m x 128o, K chunked by 64. 8 warps: warp = 32m x 64o.
// smem (dynamic, 73728B): Xh[128x72bf16 pad], Xl, Wh, Wl — each 18432B, row stride 144B.
#define SM_XH 0
#define SM_XL 18432
#define SM_WH 36864
#define SM_WL 55296
#define CONV_SMEM 73728

template <int LAYER>
__global__ __launch_bounds__(256, 2) void conv_mma(const float* __restrict__ bias)
{
    constexpr int C      = (LAYER == 2) ? O1 : O2;
    constexpr int NCHUNK = C / 64;
    constexpr int bnofs  = (LAYER == 2) ? 0 : 256;
    constexpr int stofs  = (LAYER == 2) ? 1*256*64 : 2*256*64;
    const float* __restrict__ Xin = (LAYER == 2) ? g_x1m : g_x2m;
    const unsigned* __restrict__ WhG =
        (const unsigned*)((LAYER == 2) ? (const void*)g_W1h : (const void*)g_W2h);
    const unsigned* __restrict__ WlG =
        (const unsigned*)((LAYER == 2) ? (const void*)g_W1l : (const void*)g_W2l);

    extern __shared__ __align__(16) char smc[];
    unsigned sb = smem_u32(smc);
    unsigned* Xhs = (unsigned*)(smc + SM_XH);
    unsigned* Xls = (unsigned*)(smc + SM_XL);
    unsigned* Whs = (unsigned*)(smc + SM_WH);
    unsigned* Wls = (unsigned*)(smc + SM_WL);

    int t = threadIdx.x, w = t >> 5, lane = t & 31;
    int m0 = blockIdx.x * 128;
    int o0 = blockIdx.y * 128;

    float acc[2][8][4];
    #pragma unroll
    for (int a = 0; a < 2; a++)
        #pragma unroll
        for (int b = 0; b < 8; b++)
            #pragma unroll
            for (int c = 0; c < 4; c++) acc[a][b][c] = 0.f;

    int mw = (w & 3) * 32;         // warp m offset within CTA tile
    int ow = (w >> 2) * 64;        // warp o offset within CTA tile
    // ldmatrix per-lane base addresses (byte offsets; stride 144B per row)
    unsigned aoff = sb + SM_XH + (unsigned)(mw + (lane & 15)) * 144u + ((lane & 16) ? 16u : 0u);
    unsigned boff = sb + SM_WH + (unsigned)(ow + ((lane >> 4) << 3) + (lane & 7)) * 144u
                    + ((lane & 8) ? 16u : 0u);

    for (int ck = 0; ck < NCHUNK; ck++) {
        int kc0 = ck * 64;
        // ---- stage X chunk: BN(prev)+ReLU + hi/lo split, padded rows ----
        #pragma unroll
        for (int idx = t; idx < 2048; idx += 256) {
            int row = idx >> 4, c4 = (idx & 15) << 2;
            float4 v  = *(const float4*)&Xin[(size_t)(m0 + row)*C + kc0 + c4];
            float4 A  = *(const float4*)&g_bnA[bnofs + kc0 + c4];
            float4 Cc = *(const float4*)&g_bnC[bnofs + kc0 + c4];
            float x0 = fmaxf(fmaf(A.x, v.x, Cc.x), 0.f);
            float x1 = fmaxf(fmaf(A.y, v.y, Cc.y), 0.f);
            float x2 = fmaxf(fmaf(A.z, v.z, Cc.z), 0.f);
            float x3 = fmaxf(fmaf(A.w, v.w, Cc.w), 0.f);
            __nv_bfloat16 h0,l0,h1,l1,h2,l2,h3,l3;
            split_bf16(x0,h0,l0); split_bf16(x1,h1,l1);
            split_bf16(x2,h2,l2); split_bf16(x3,h3,l3);
            uint2 hp; hp.x = bfpack(h0,h1); hp.y = bfpack(h2,h3);
            uint2 lp; lp.x = bfpack(l0,l1); lp.y = bfpack(l2,l3);
            *(uint2*)&Xhs[row*36 + (c4 >> 1)] = hp;
            *(uint2*)&Xls[row*36 + (c4 >> 1)] = lp;
        }
        // ---- stage W chunk (pre-split bf16), padded rows ----
        #pragma unroll
        for (int idx = t; idx < 1024; idx += 256) {
            int row = idx >> 3, cu = (idx & 7) << 2;
            size_t src = (size_t)(o0 + row)*(C/2) + (kc0 >> 1) + cu;
            *(uint4*)&Whs[row*36 + cu] = *(const uint4*)&WhG[src];
            *(uint4*)&Wls[row*36 + cu] = *(const uint4*)&WlG[src];
        }
        __syncthreads();

        // ---- compute: 4 k-steps of m16n8k16, hi/lo 3-pass ----
        #pragma unroll
        for (int kt = 0; kt < 4; kt++) {
            unsigned ab = aoff + kt*32;
            unsigned ah0[4], ah1[4], al0[4], al1[4];
            ldsm4(ah0, ab);
            ldsm4(ah1, ab + 16*144);
            ldsm4(al0, ab + SM_XL);
            ldsm4(al1, ab + SM_XL + 16*144);
            #pragma unroll
            for (int np = 0; np < 4; np++) {
                unsigned bb = boff + np*(16*144) + kt*32;
                unsigned bh[4], bl[4];
                ldsm4(bh, bb);
                ldsm4(bl, bb + (SM_WL - SM_WH));
                // n-tile 2np
                mma16816(acc[0][2*np],   ah0, bh[0], bh[1]);
                mma16816(acc[0][2*np],   ah0, bl[0], bl[1]);
                mma16816(acc[0][2*np],   al0, bh[0], bh[1]);
                mma16816(acc[1][2*np],   ah1, bh[0], bh[1]);
                mma16816(acc[1][2*np],   ah1, bl[0], bl[1]);
                mma16816(acc[1][2*np],   al1, bh[0], bh[1]);
                // n-tile 2np+1
                mma16816(acc[0][2*np+1], ah0, bh[2], bh[3]);
                mma16816(acc[0][2*np+1], ah0, bl[2], bl[3]);
                mma16816(acc[0][2*np+1], al0, bh[2], bh[3]);
                mma16816(acc[1][2*np+1], ah1, bh[2], bh[3]);
                mma16816(acc[1][2*np+1], ah1, bl[2], bl[3]);
                mma16816(acc[1][2*np+1], al1, bh[2], bh[3]);
            }
        }
        __syncthreads();
    }

    // ---- epilogue: bias, stats, store (L2) or max/min (L3) ----
    int g  = lane >> 2;
    int c2 = (lane & 3) << 1;
    int bslot = blockIdx.x & 63;
    #pragma unroll
    for (int nt = 0; nt < 8; nt++) {
        int col = o0 + ow + nt*8 + c2;          // global o for cols (col, col+1)
        float2 bv = *(const float2*)&bias[col];
        float v00 = acc[0][nt][0] + bv.x, v01 = acc[0][nt][1] + bv.y;
        float v10 = acc[0][nt][2] + bv.x, v11 = acc[0][nt][3] + bv.y;
        float w00 = acc[1][nt][0] + bv.x, w01 = acc[1][nt][1] + bv.y;
        float w10 = acc[1][nt][2] + bv.x, w11 = acc[1][nt][3] + bv.y;

        if (LAYER == 2) {
            int r = m0 + mw + g;
            *(float2*)&g_x2m[(size_t)(r     )*O2 + col] = make_float2(v00, v01);
            *(float2*)&g_x2m[(size_t)(r +  8)*O2 + col] = make_float2(v10, v11);
            *(float2*)&g_x2m[(size_t)(r + 16)*O2 + col] = make_float2(w00, w01);
            *(float2*)&g_x2m[(size_t)(r + 24)*O2 + col] = make_float2(w10, w11);
        }

        float s0 = rsum3(v00 + v10 + w00 + w10);
        float s1 = rsum3(v01 + v11 + w01 + w11);
        float q0 = rsum3(v00*v00 + v10*v10 + w00*w00 + w10*w10);
        float q1 = rsum3(v01*v01 + v11*v11 + w01*w01 + w11*w11);

        float mx0 = 0.f, mx1 = 0.f, mn0 = 0.f, mn1 = 0.f;
        if (LAYER == 3) {
            mx0 = rmax3(fmaxf(fmaxf(v00, v10), fmaxf(w00, w10)));
            mn0 = rmin3(fminf(fminf(v00, v10), fminf(w00, w10)));
            mx1 = rmax3(fmaxf(fmaxf(v01, v11), fmaxf(w01, w11)));
            mn1 = rmin3(fminf(fminf(v01, v11), fminf(w01, w11)));
        }
        if (lane < 4) {
            atomicAdd(&g_statS[stofs + (col    )*64 + bslot], s0);
            atomicAdd(&g_statS[stofs + (col + 1)*64 + bslot], s1);
            atomicAdd(&g_statQ[stofs + (col    )*64 + bslot], q0);
            atomicAdd(&g_statQ[stofs + (col + 1)*64 + bslot], q1);
            if (LAYER == 3) {
                int bp = (m0 + mw) >> 5;
                *(float2*)&g_xmaxT[bp*O3 + col] = make_float2(mx0, mx1);
                *(float2*)&g_xminT[bp*O3 + col] = make_float2(mn0, mn1);
            }
        }
    }
}

// ---------------- final: BN2 affine + ReLU on max/min, transpose to output ----------------
__global__ void finalize_out(float* __restrict__ out, int ofs) {
    __shared__ float tile[32][33];
    int o0  = blockIdx.y * 32;
    int bp0 = blockIdx.x * 32;
    int tx = threadIdx.x, ty = threadIdx.y;   // 32 x 8
    float a = g_bnA[512 + o0 + tx], c = g_bnC[512 + o0 + tx];
    #pragma unroll
    for (int i = 0; i < 32; i += 8) {
        int bp = bp0 + ty + i;
        float mx = g_xmaxT[bp*O3 + o0 + tx];
        float mn = g_xminT[bp*O3 + o0 + tx];
        float x = (a >= 0.f) ? mx : mn;
        tile[ty + i][tx] = fmaxf(fmaf(a, x, c), 0.f);
    }
    __syncthreads();
    int b  = bp0 >> 10;
    int p0 = bp0 & 1023;
    #pragma unroll
    for (int i = 0; i < 32; i += 8) {
        int o = o0 + ty + i;
        out[ofs + ((size_t)b*O3 + o)*NPTS + p0 + tx] = tile[tx][ty + i];
    }
}

// ---------------- launch ----------------
extern "C" void kernel_launch(void* const* d_in, const int* in_sizes, int n_in,
                              void* d_out, int out_size) {
    const float* xyz    = (const float*)d_in[0];
    const float* points = (const float*)d_in[1];
    const int*   sidx   = (const int*)  d_in[2];
    const int*   nidx   = (const int*)  d_in[3];
    const float* W0 = (const float*)d_in[4],  *b0 = (const float*)d_in[5];
    const float* g0 = (const float*)d_in[6],  *be0 = (const float*)d_in[7];
    const float* W1 = (const float*)d_in[8],  *b1 = (const float*)d_in[9];
    const float* g1 = (const float*)d_in[10], *be1 = (const float*)d_in[11];
    const float* W2 = (const float*)d_in[12], *b2 = (const float*)d_in[13];
    const float* g2 = (const float*)d_in[14], *be2 = (const float*)d_in[15];
    float* out = (float*)d_out;

    int xyz_ofs = (out_size > O3*BPTOT) ? (out_size - O3*BPTOT) : 0;

    cudaFuncSetAttribute(conv_mma<2>, cudaFuncAttributeMaxDynamicSharedMemorySize, CONV_SMEM);
    cudaFuncSetAttribute(conv_mma<3>, cudaFuncAttributeMaxDynamicSharedMemorySize, CONV_SMEM);

    zero_stats<<<(3*256*64 + 255)/256, 256>>>();
    transpose_pts<<<dim3(NN/32, CF/32, BB), dim3(32, 8)>>>(points);
    convert_w<<<(O3*O2 + 255)/256, 256>>>(W1, W2);
    gather_conv1<<<BPTOT, 256>>>(xyz, sidx, nidx, W0, b0, out, xyz_ofs);
    bn_finalize<<<1, 64>>>(0, O1, g0, be0);
    conv_mma<2><<<dim3(MTOT/128, 1), 256, CONV_SMEM>>>(b1);
    bn_finalize<<<1, 128>>>(1, O2, g1, be1);
    conv_mma<3><<<dim3(MTOT/128, O3/128), 256, CONV_SMEM>>>(b2);
    bn_finalize<<<1, 256>>>(2, O3, g2, be2);
    finalize_out<<<dim3(BPTOT/32, O3/32), dim3(32, 8)>>>(out, xyz_ofs);
}

// round 16
// speedup vs baseline: 3.5931x; 1.1933x over previous
#include <cuda_runtime.h>
#include <cuda_bf16.h>

// Problem constants
#define BB   8
#define NN   4096
#define NPTS 1024
#define NS   32
#define CF   64
#define C0   67
#define O1   64
#define O2   128
#define O3   256
#define MTOT (BB*NPTS*NS)  // 262144
#define BPTOT (BB*NPTS)    // 8192
#define BNEPS 1e-5f

// ---------------- scratch (device globals; no allocation allowed) ----------------
__device__ __align__(16) float g_P[(size_t)BB*NN*O1];     // per-point conv1 partial [b,n,o]
__device__ __align__(16) float g_x1m[(size_t)MTOT*O1];    // layer1 raw, m-major [m][64]
__device__ __align__(16) float g_x2m[(size_t)MTOT*O2];    // layer2 raw, m-major [m][128]
__device__ __align__(16) float g_xmaxT[BPTOT*O3];         // [bp][256]
__device__ __align__(16) float g_xminT[BPTOT*O3];         // [bp][256]
__device__ __align__(16) float g_statS[3*256*64];
__device__ __align__(16) float g_statQ[3*256*64];
__device__ __align__(16) float g_bnA[3*256];
__device__ __align__(16) float g_bnC[3*256];
__device__ __align__(16) __nv_bfloat16 g_W1h[O2*O1], g_W1l[O2*O1];   // [o][c]
__device__ __align__(16) __nv_bfloat16 g_W2h[O3*O2], g_W2l[O3*O2];   // [o][c]

// ---------------- helpers (plain sm_80-class PTX only) ----------------
static __device__ __forceinline__ unsigned smem_u32(const void* p) {
    unsigned a;
    asm("{ .reg .u64 t; cvta.to.shared.u64 t, %1; cvt.u32.u64 %0, t; }" : "=r"(a) : "l"(p));
    return a;
}
static __device__ __forceinline__ void ldsm4(unsigned* r, unsigned addr) {
    asm volatile("ldmatrix.sync.aligned.m8n8.x4.shared.b16 {%0,%1,%2,%3}, [%4];"
        : "=r"(r[0]), "=r"(r[1]), "=r"(r[2]), "=r"(r[3]) : "r"(addr));
}
static __device__ __forceinline__ void mma16816(float* d, const unsigned* a,
                                                unsigned b0, unsigned b1) {
    asm volatile("mma.sync.aligned.m16n8k16.row.col.f32.bf16.bf16.f32 "
        "{%0,%1,%2,%3}, {%4,%5,%6,%7}, {%8,%9}, {%0,%1,%2,%3};"
        : "+f"(d[0]), "+f"(d[1]), "+f"(d[2]), "+f"(d[3])
        : "r"(a[0]), "r"(a[1]), "r"(a[2]), "r"(a[3]), "r"(b0), "r"(b1));
}
static __device__ __forceinline__ unsigned bfpack(__nv_bfloat16 a, __nv_bfloat16 b) {
    unsigned short ua = *(unsigned short*)&a, ub = *(unsigned short*)&b;
    return (unsigned)ua | ((unsigned)ub << 16);
}
static __device__ __forceinline__ void split_bf16(float x, __nv_bfloat16& h, __nv_bfloat16& l) {
    h = __float2bfloat16_rn(x);
    l = __float2bfloat16_rn(x - __bfloat162float(h));
}
static __device__ __forceinline__ float rsum3(float v) {
    v += __shfl_xor_sync(0xffffffffu, v, 4);
    v += __shfl_xor_sync(0xffffffffu, v, 8);
    v += __shfl_xor_sync(0xffffffffu, v, 16);
    return v;
}
static __device__ __forceinline__ float rmax3(float v) {
    v = fmaxf(v, __shfl_xor_sync(0xffffffffu, v, 4));
    v = fmaxf(v, __shfl_xor_sync(0xffffffffu, v, 8));
    v = fmaxf(v, __shfl_xor_sync(0xffffffffu, v, 16));
    return v;
}
static __device__ __forceinline__ float rmin3(float v) {
    v = fminf(v, __shfl_xor_sync(0xffffffffu, v, 4));
    v = fminf(v, __shfl_xor_sync(0xffffffffu, v, 8));
    v = fminf(v, __shfl_xor_sync(0xffffffffu, v, 16));
    return v;
}

// ---------------- utility kernels ----------------
__global__ void zero_stats() {
    int i = blockIdx.x * blockDim.x + threadIdx.x;
    if (i < 3*256*64) { g_statS[i] = 0.f; g_statQ[i] = 0.f; }
}

__global__ void convert_w(const float* __restrict__ W1, const float* __restrict__ W2) {
    int t = blockIdx.x * 256 + threadIdx.x;
    if (t < O2*O1) {
        __nv_bfloat16 h, l; split_bf16(W1[t], h, l);
        g_W1h[t] = h; g_W1l[t] = l;
    }
    if (t < O3*O2) {
        __nv_bfloat16 h, l; split_bf16(W2[t], h, l);
        g_W2h[t] = h; g_W2l[t] = l;
    }
}

// ---------------- precompute P[b,n,o] = sum_k W0[o,k] * feat67(b,n,k) ----------------
// feat67 = [xyz(3), points(64)]. One block per 32 points; warp w -> o in [8w,8w+8).
__global__ __launch_bounds__(256) void precompute_P(
    const float* __restrict__ xyz, const float* __restrict__ points,
    const float* __restrict__ W0)
{
    int blk = blockIdx.x;
    int b  = blk >> 7;             // NN/32 = 128 blocks per batch
    int n0 = (blk & 127) * 32;
    __shared__ __align__(16) float x0s[C0][33];
    __shared__ __align__(16) float W0s[C0][O1];

    int t = threadIdx.x;
    for (int e = t; e < C0*O1; e += 256) {
        int o = e & 63, c = e >> 6;
        W0s[c][o] = W0[o*C0 + c];
    }
    {
        int col = t & 31, r0 = t >> 5;
        for (int r = r0; r < C0; r += 8)
            x0s[r][col] = (r < 3)
                ? xyz[((size_t)b*NN + n0 + col)*3 + r]
                : points[(size_t)b*CF*NN + (size_t)(r - 3)*NN + n0 + col];
    }
    __syncthreads();

    int w = t >> 5, lane = t & 31, o0 = w * 8;
    float acc[8];
    #pragma unroll
    for (int i = 0; i < 8; i++) acc[i] = 0.f;
    #pragma unroll
    for (int c = 0; c < C0; c++) {
        float xv = x0s[c][lane];
        float4 wa = *(const float4*)&W0s[c][o0];
        float4 wb = *(const float4*)&W0s[c][o0 + 4];
        acc[0] = fmaf(wa.x, xv, acc[0]);
        acc[1] = fmaf(wa.y, xv, acc[1]);
        acc[2] = fmaf(wa.z, xv, acc[2]);
        acc[3] = fmaf(wa.w, xv, acc[3]);
        acc[4] = fmaf(wb.x, xv, acc[4]);
        acc[5] = fmaf(wb.y, xv, acc[5]);
        acc[6] = fmaf(wb.z, xv, acc[6]);
        acc[7] = fmaf(wb.w, xv, acc[7]);
    }
    size_t base = ((size_t)b*NN + n0 + lane)*O1 + o0;
    *(float4*)&g_P[base]     = make_float4(acc[0], acc[1], acc[2], acc[3]);
    *(float4*)&g_P[base + 4] = make_float4(acc[4], acc[5], acc[6], acc[7]);
}

// ---------------- layer 1: gather P rows + per-bp constant + stats ----------------
// x1[bp,s,o] = P[b, nbr, o] + (b0[o] - W0xyz[o]·ctr)
__global__ __launch_bounds__(256) void gather_add(
    const float* __restrict__ xyz, const int* __restrict__ sample_idx,
    const int* __restrict__ neighbor_idx, const float* __restrict__ W0,
    const float* __restrict__ b0, float* __restrict__ out, int xyz_ofs)
{
    int bp = blockIdx.x;
    int b = bp >> 10;
    __shared__ int   sidx[NS];
    __shared__ float Qp[O1];
    __shared__ float ctr[3];

    int t = threadIdx.x;
    if (t < NS) sidx[t] = neighbor_idx[bp*NS + t];
    if (t == 0) {
        int sp = sample_idx[bp];
        #pragma unroll
        for (int k = 0; k < 3; k++) {
            float v = xyz[((size_t)b*NN + sp)*3 + k];
            ctr[k] = v;
            if (xyz_ofs > 0) out[bp*3 + k] = v;
        }
    }
    __syncthreads();
    if (t < O1) {
        const float* wr = &W0[t*C0];
        Qp[t] = b0[t] - (wr[0]*ctr[0] + wr[1]*ctr[1] + wr[2]*ctr[2]);
    }
    __syncthreads();

    int w = t >> 5, lane = t & 31, o0 = w * 8;
    int idx = sidx[lane];
    const float4* prow = (const float4*)&g_P[((size_t)b*NN + idx)*O1 + o0];
    float4 v0 = prow[0], v1 = prow[1];
    float acc[8];
    acc[0] = v0.x + Qp[o0];     acc[1] = v0.y + Qp[o0 + 1];
    acc[2] = v0.z + Qp[o0 + 2]; acc[3] = v0.w + Qp[o0 + 3];
    acc[4] = v1.x + Qp[o0 + 4]; acc[5] = v1.y + Qp[o0 + 5];
    acc[6] = v1.z + Qp[o0 + 6]; acc[7] = v1.w + Qp[o0 + 7];

    int m = bp*NS + lane;
    *(float4*)&g_x1m[(size_t)m*O1 + o0]     = make_float4(acc[0], acc[1], acc[2], acc[3]);
    *(float4*)&g_x1m[(size_t)m*O1 + o0 + 4] = make_float4(acc[4], acc[5], acc[6], acc[7]);

    #pragma unroll
    for (int i = 0; i < 8; i++) {
        float s1 = acc[i], s2 = acc[i]*acc[i];
        #pragma unroll
        for (int d = 16; d; d >>= 1) {
            s1 += __shfl_xor_sync(0xffffffffu, s1, d);
            s2 += __shfl_xor_sync(0xffffffffu, s2, d);
        }
        if (lane == 0) {
            int slot = (o0 + i)*64 + (bp & 63);
            atomicAdd(&g_statS[slot], s1);
            atomicAdd(&g_statQ[slot], s2);
        }
    }
}

// ---------------- BN finalize ----------------
__global__ void bn_finalize(int layer, int O, const float* __restrict__ gamma,
                            const float* __restrict__ beta)
{
    int o = blockIdx.x * blockDim.x + threadIdx.x;
    if (o >= O) return;
    float s = 0.f, q = 0.f;
    int base = layer*256*64 + o*64;
    #pragma unroll 8
    for (int k = 0; k < 64; k++) { s += g_statS[base + k]; q += g_statQ[base + k]; }
    float invM = 1.0f / (float)MTOT;
    float mu   = s * invM;
    float var  = q * invM - mu*mu;
    float a    = gamma[o] * rsqrtf(var + BNEPS);
    g_bnA[layer*256 + o] = a;
    g_bnC[layer*256 + o] = beta[o] - a*mu;
}

// ---------------- layers 2/3: warp-MMA (mma.sync bf16, hi/lo 3-pass) ----------------
// CTA tile: 128m x 128o, K chunked by 64. 8 warps: warp = 32m x 64o.
// smem (dynamic, 73728B): Xh[128x72bf16 pad], Xl, Wh, Wl — each 18432B, row stride 144B.
#define SM_XH 0
#define SM_XL 18432
#define SM_WH 36864
#define SM_WL 55296
#define CONV_SMEM 73728

template <int LAYER>
__global__ __launch_bounds__(256, 2) void conv_mma(const float* __restrict__ bias)
{
    constexpr int C      = (LAYER == 2) ? O1 : O2;
    constexpr int NCHUNK = C / 64;
    constexpr int bnofs  = (LAYER == 2) ? 0 : 256;
    constexpr int stofs  = (LAYER == 2) ? 1*256*64 : 2*256*64;
    const float* __restrict__ Xin = (LAYER == 2) ? g_x1m : g_x2m;
    const unsigned* __restrict__ WhG =
        (const unsigned*)((LAYER == 2) ? (const void*)g_W1h : (const void*)g_W2h);
    const unsigned* __restrict__ WlG =
        (const unsigned*)((LAYER == 2) ? (const void*)g_W1l : (const void*)g_W2l);

    extern __shared__ __align__(16) char smc[];
    unsigned sb = smem_u32(smc);
    unsigned* Xhs = (unsigned*)(smc + SM_XH);
    unsigned* Xls = (unsigned*)(smc + SM_XL);
    unsigned* Whs = (unsigned*)(smc + SM_WH);
    unsigned* Wls = (unsigned*)(smc + SM_WL);

    int t = threadIdx.x, w = t >> 5, lane = t & 31;
    int m0 = blockIdx.x * 128;
    int o0 = blockIdx.y * 128;

    float acc[2][8][4];
    #pragma unroll
    for (int a = 0; a < 2; a++)
        #pragma unroll
        for (int b = 0; b < 8; b++)
            #pragma unroll
            for (int c = 0; c < 4; c++) acc[a][b][c] = 0.f;

    int mw = (w & 3) * 32;         // warp m offset within CTA tile
    int ow = (w >> 2) * 64;        // warp o offset within CTA tile
    unsigned aoff = sb + SM_XH + (unsigned)(mw + (lane & 15)) * 144u + ((lane & 16) ? 16u : 0u);
    unsigned boff = sb + SM_WH + (unsigned)(ow + ((lane >> 4) << 3) + (lane & 7)) * 144u
                    + ((lane & 8) ? 16u : 0u);

    for (int ck = 0; ck < NCHUNK; ck++) {
        int kc0 = ck * 64;
        // ---- stage X chunk: BN(prev)+ReLU + hi/lo split, padded rows ----
        #pragma unroll
        for (int idx = t; idx < 2048; idx += 256) {
            int row = idx >> 4, c4 = (idx & 15) << 2;
            float4 v  = *(const float4*)&Xin[(size_t)(m0 + row)*C + kc0 + c4];
            float4 A  = *(const float4*)&g_bnA[bnofs + kc0 + c4];
            float4 Cc = *(const float4*)&g_bnC[bnofs + kc0 + c4];
            float x0 = fmaxf(fmaf(A.x, v.x, Cc.x), 0.f);
            float x1 = fmaxf(fmaf(A.y, v.y, Cc.y), 0.f);
            float x2 = fmaxf(fmaf(A.z, v.z, Cc.z), 0.f);
            float x3 = fmaxf(fmaf(A.w, v.w, Cc.w), 0.f);
            __nv_bfloat16 h0,l0,h1,l1,h2,l2,h3,l3;
            split_bf16(x0,h0,l0); split_bf16(x1,h1,l1);
            split_bf16(x2,h2,l2); split_bf16(x3,h3,l3);
            uint2 hp; hp.x = bfpack(h0,h1); hp.y = bfpack(h2,h3);
            uint2 lp; lp.x = bfpack(l0,l1); lp.y = bfpack(l2,l3);
            *(uint2*)&Xhs[row*36 + (c4 >> 1)] = hp;
            *(uint2*)&Xls[row*36 + (c4 >> 1)] = lp;
        }
        // ---- stage W chunk (pre-split bf16), padded rows ----
        #pragma unroll
        for (int idx = t; idx < 1024; idx += 256) {
            int row = idx >> 3, cu = (idx & 7) << 2;
            size_t src = (size_t)(o0 + row)*(C/2) + (kc0 >> 1) + cu;
            *(uint4*)&Whs[row*36 + cu] = *(const uint4*)&WhG[src];
            *(uint4*)&Wls[row*36 + cu] = *(const uint4*)&WlG[src];
        }
        __syncthreads();

        // ---- compute: 4 k-steps of m16n8k16, hi/lo 3-pass ----
        #pragma unroll
        for (int kt = 0; kt < 4; kt++) {
            unsigned ab = aoff + kt*32;
            unsigned ah0[4], ah1[4], al0[4], al1[4];
            ldsm4(ah0, ab);
            ldsm4(ah1, ab + 16*144);
            ldsm4(al0, ab + SM_XL);
            ldsm4(al1, ab + SM_XL + 16*144);
            #pragma unroll
            for (int np = 0; np < 4; np++) {
                unsigned bb = boff + np*(16*144) + kt*32;
                unsigned bh[4], bl[4];
                ldsm4(bh, bb);
                ldsm4(bl, bb + (SM_WL - SM_WH));
                mma16816(acc[0][2*np],   ah0, bh[0], bh[1]);
                mma16816(acc[0][2*np],   ah0, bl[0], bl[1]);
                mma16816(acc[0][2*np],   al0, bh[0], bh[1]);
                mma16816(acc[1][2*np],   ah1, bh[0], bh[1]);
                mma16816(acc[1][2*np],   ah1, bl[0], bl[1]);
                mma16816(acc[1][2*np],   al1, bh[0], bh[1]);
                mma16816(acc[0][2*np+1], ah0, bh[2], bh[3]);
                mma16816(acc[0][2*np+1], ah0, bl[2], bl[3]);
                mma16816(acc[0][2*np+1], al0, bh[2], bh[3]);
                mma16816(acc[1][2*np+1], ah1, bh[2], bh[3]);
                mma16816(acc[1][2*np+1], ah1, bl[2], bl[3]);
                mma16816(acc[1][2*np+1], al1, bh[2], bh[3]);
            }
        }
        __syncthreads();
    }

    // ---- epilogue: bias, stats, store (L2) or max/min (L3) ----
    int g  = lane >> 2;
    int c2 = (lane & 3) << 1;
    int bslot = blockIdx.x & 63;
    #pragma unroll
    for (int nt = 0; nt < 8; nt++) {
        int col = o0 + ow + nt*8 + c2;
        float2 bv = *(const float2*)&bias[col];
        float v00 = acc[0][nt][0] + bv.x, v01 = acc[0][nt][1] + bv.y;
        float v10 = acc[0][nt][2] + bv.x, v11 = acc[0][nt][3] + bv.y;
        float w00 = acc[1][nt][0] + bv.x, w01 = acc[1][nt][1] + bv.y;
        float w10 = acc[1][nt][2] + bv.x, w11 = acc[1][nt][3] + bv.y;

        if (LAYER == 2) {
            int r = m0 + mw + g;
            *(float2*)&g_x2m[(size_t)(r     )*O2 + col] = make_float2(v00, v01);
            *(float2*)&g_x2m[(size_t)(r +  8)*O2 + col] = make_float2(v10, v11);
            *(float2*)&g_x2m[(size_t)(r + 16)*O2 + col] = make_float2(w00, w01);
            *(float2*)&g_x2m[(size_t)(r + 24)*O2 + col] = make_float2(w10, w11);
        }

        float s0 = rsum3(v00 + v10 + w00 + w10);
        float s1 = rsum3(v01 + v11 + w01 + w11);
        float q0 = rsum3(v00*v00 + v10*v10 + w00*w00 + w10*w10);
        float q1 = rsum3(v01*v01 + v11*v11 + w01*w01 + w11*w11);

        float mx0 = 0.f, mx1 = 0.f, mn0 = 0.f, mn1 = 0.f;
        if (LAYER == 3) {
            mx0 = rmax3(fmaxf(fmaxf(v00, v10), fmaxf(w00, w10)));
            mn0 = rmin3(fminf(fminf(v00, v10), fminf(w00, w10)));
            mx1 = rmax3(fmaxf(fmaxf(v01, v11), fmaxf(w01, w11)));
            mn1 = rmin3(fminf(fminf(v01, v11), fminf(w01, w11)));
        }
        if (lane < 4) {
            atomicAdd(&g_statS[stofs + (col    )*64 + bslot], s0);
            atomicAdd(&g_statS[stofs + (col + 1)*64 + bslot], s1);
            atomicAdd(&g_statQ[stofs + (col    )*64 + bslot], q0);
            atomicAdd(&g_statQ[stofs + (col + 1)*64 + bslot], q1);
            if (LAYER == 3) {
                int bp = (m0 + mw) >> 5;
                *(float2*)&g_xmaxT[bp*O3 + col] = make_float2(mx0, mx1);
                *(float2*)&g_xminT[bp*O3 + col] = make_float2(mn0, mn1);
            }
        }
    }
}

// ---------------- final: BN2 affine + ReLU on max/min, transpose to output ----------------
__global__ void finalize_out(float* __restrict__ out, int ofs) {
    __shared__ float tile[32][33];
    int o0  = blockIdx.y * 32;
    int bp0 = blockIdx.x * 32;
    int tx = threadIdx.x, ty = threadIdx.y;   // 32 x 8
    float a = g_bnA[512 + o0 + tx], c = g_bnC[512 + o0 + tx];
    #pragma unroll
    for (int i = 0; i < 32; i += 8) {
        int bp = bp0 + ty + i;
        float mx = g_xmaxT[bp*O3 + o0 + tx];
        float mn = g_xminT[bp*O3 + o0 + tx];
        float x = (a >= 0.f) ? mx : mn;
        tile[ty + i][tx] = fmaxf(fmaf(a, x, c), 0.f);
    }
    __syncthreads();
    int b  = bp0 >> 10;
    int p0 = bp0 & 1023;
    #pragma unroll
    for (int i = 0; i < 32; i += 8) {
        int o = o0 + ty + i;
        out[ofs + ((size_t)b*O3 + o)*NPTS + p0 + tx] = tile[tx][ty + i];
    }
}

// ---------------- launch ----------------
extern "C" void kernel_launch(void* const* d_in, const int* in_sizes, int n_in,
                              void* d_out, int out_size) {
    const float* xyz    = (const float*)d_in[0];
    const float* points = (const float*)d_in[1];
    const int*   sidx   = (const int*)  d_in[2];
    const int*   nidx   = (const int*)  d_in[3];
    const float* W0 = (const float*)d_in[4],  *b0 = (const float*)d_in[5];
    const float* g0 = (const float*)d_in[6],  *be0 = (const float*)d_in[7];
    const float* W1 = (const float*)d_in[8],  *b1 = (const float*)d_in[9];
    const float* g1 = (const float*)d_in[10], *be1 = (const float*)d_in[11];
    const float* W2 = (const float*)d_in[12], *b2 = (const float*)d_in[13];
    const float* g2 = (const float*)d_in[14], *be2 = (const float*)d_in[15];
    float* out = (float*)d_out;

    int xyz_ofs = (out_size > O3*BPTOT) ? (out_size - O3*BPTOT) : 0;

    cudaFuncSetAttribute(conv_mma<2>, cudaFuncAttributeMaxDynamicSharedMemorySize, CONV_SMEM);
    cudaFuncSetAttribute(conv_mma<3>, cudaFuncAttributeMaxDynamicSharedMemorySize, CONV_SMEM);

    zero_stats<<<(3*256*64 + 255)/256, 256>>>();
    convert_w<<<(O3*O2 + 255)/256, 256>>>(W1, W2);
    precompute_P<<<(BB*NN)/32, 256>>>(xyz, points, W0);
    gather_add<<<BPTOT, 256>>>(xyz, sidx, nidx, W0, b0, out, xyz_ofs);
    bn_finalize<<<1, 64>>>(0, O1, g0, be0);
    conv_mma<2><<<dim3(MTOT/128, 1), 256, CONV_SMEM>>>(b1);
    bn_finalize<<<1, 128>>>(1, O2, g1, be1);
    conv_mma<3><<<dim3(MTOT/128, O3/128), 256, CONV_SMEM>>>(b2);
    bn_finalize<<<1, 256>>>(2, O3, g2, be2);
    finalize_out<<<dim3(BPTOT/32, O3/32), dim3(32, 8)>>>(out, xyz_ofs);
}

// round 17
// speedup vs baseline: 4.0262x; 1.1205x over previous
#include <cuda_runtime.h>
#include <cuda_bf16.h>

// Problem constants
#define BB   8
#define NN   4096
#define NPTS 1024
#define NS   32
#define CF   64
#define C0   67
#define O1   64
#define O2   128
#define O3   256
#define MTOT (BB*NPTS*NS)  // 262144
#define BPTOT (BB*NPTS)    // 8192
#define BNEPS 1e-5f

// ---------------- scratch (device globals; no allocation allowed) ----------------
__device__ __align__(16) float g_P[(size_t)BB*NN*O1];     // per-point conv1 partial [b,n,o]  8.4MB (L2-resident)
__device__ __align__(16) float g_Qp[(size_t)BPTOT*O1];    // per-bp conv1 constant [bp][o]    2MB
__device__ __align__(16) float g_x2m[(size_t)MTOT*O2];    // layer2 raw, m-major [m][128]
__device__ __align__(16) float g_xmaxT[BPTOT*O3];         // [bp][256]
__device__ __align__(16) float g_xminT[BPTOT*O3];         // [bp][256]
__device__ __align__(16) float g_statS[3*256*64];
__device__ __align__(16) float g_statQ[3*256*64];
__device__ __align__(16) float g_bnA[3*256];
__device__ __align__(16) float g_bnC[3*256];
__device__ __align__(16) __nv_bfloat16 g_W1h[O2*O1], g_W1l[O2*O1];   // [o][c]
__device__ __align__(16) __nv_bfloat16 g_W2h[O3*O2], g_W2l[O3*O2];   // [o][c]

// ---------------- helpers (plain sm_80-class PTX only) ----------------
static __device__ __forceinline__ unsigned smem_u32(const void* p) {
    unsigned a;
    asm("{ .reg .u64 t; cvta.to.shared.u64 t, %1; cvt.u32.u64 %0, t; }" : "=r"(a) : "l"(p));
    return a;
}
static __device__ __forceinline__ void ldsm4(unsigned* r, unsigned addr) {
    asm volatile("ldmatrix.sync.aligned.m8n8.x4.shared.b16 {%0,%1,%2,%3}, [%4];"
        : "=r"(r[0]), "=r"(r[1]), "=r"(r[2]), "=r"(r[3]) : "r"(addr));
}
static __device__ __forceinline__ void mma16816(float* d, const unsigned* a,
                                                unsigned b0, unsigned b1) {
    asm volatile("mma.sync.aligned.m16n8k16.row.col.f32.bf16.bf16.f32 "
        "{%0,%1,%2,%3}, {%4,%5,%6,%7}, {%8,%9}, {%0,%1,%2,%3};"
        : "+f"(d[0]), "+f"(d[1]), "+f"(d[2]), "+f"(d[3])
        : "r"(a[0]), "r"(a[1]), "r"(a[2]), "r"(a[3]), "r"(b0), "r"(b1));
}
static __device__ __forceinline__ unsigned bfpack(__nv_bfloat16 a, __nv_bfloat16 b) {
    unsigned short ua = *(unsigned short*)&a, ub = *(unsigned short*)&b;
    return (unsigned)ua | ((unsigned)ub << 16);
}
static __device__ __forceinline__ void split_bf16(float x, __nv_bfloat16& h, __nv_bfloat16& l) {
    h = __float2bfloat16_rn(x);
    l = __float2bfloat16_rn(x - __bfloat162float(h));
}
static __device__ __forceinline__ float rsum3(float v) {
    v += __shfl_xor_sync(0xffffffffu, v, 4);
    v += __shfl_xor_sync(0xffffffffu, v, 8);
    v += __shfl_xor_sync(0xffffffffu, v, 16);
    return v;
}
static __device__ __forceinline__ float rmax3(float v) {
    v = fmaxf(v, __shfl_xor_sync(0xffffffffu, v, 4));
    v = fmaxf(v, __shfl_xor_sync(0xffffffffu, v, 8));
    v = fmaxf(v, __shfl_xor_sync(0xffffffffu, v, 16));
    return v;
}
static __device__ __forceinline__ float rmin3(float v) {
    v = fminf(v, __shfl_xor_sync(0xffffffffu, v, 4));
    v = fminf(v, __shfl_xor_sync(0xffffffffu, v, 8));
    v = fminf(v, __shfl_xor_sync(0xffffffffu, v, 16));
    return v;
}

// ---------------- utility kernels ----------------
__global__ void zero_stats() {
    int i = blockIdx.x * blockDim.x + threadIdx.x;
    if (i < 3*256*64) { g_statS[i] = 0.f; g_statQ[i] = 0.f; }
}

__global__ void convert_w(const float* __restrict__ W1, const float* __restrict__ W2) {
    int t = blockIdx.x * 256 + threadIdx.x;
    if (t < O2*O1) {
        __nv_bfloat16 h, l; split_bf16(W1[t], h, l);
        g_W1h[t] = h; g_W1l[t] = l;
    }
    if (t < O3*O2) {
        __nv_bfloat16 h, l; split_bf16(W2[t], h, l);
        g_W2h[t] = h; g_W2l[t] = l;
    }
}

// ---------------- precompute P[b,n,o] = sum_k W0[o,k] * feat67(b,n,k) ----------------
__global__ __launch_bounds__(256) void precompute_P(
    const float* __restrict__ xyz, const float* __restrict__ points,
    const float* __restrict__ W0)
{
    int blk = blockIdx.x;
    int b  = blk >> 7;             // NN/32 = 128 blocks per batch
    int n0 = (blk & 127) * 32;
    __shared__ __align__(16) float x0s[C0][33];
    __shared__ __align__(16) float W0s[C0][O1];

    int t = threadIdx.x;
    for (int e = t; e < C0*O1; e += 256) {
        int o = e & 63, c = e >> 6;
        W0s[c][o] = W0[o*C0 + c];
    }
    {
        int col = t & 31, r0 = t >> 5;
        for (int r = r0; r < C0; r += 8)
            x0s[r][col] = (r < 3)
                ? xyz[((size_t)b*NN + n0 + col)*3 + r]
                : points[(size_t)b*CF*NN + (size_t)(r - 3)*NN + n0 + col];
    }
    __syncthreads();

    int w = t >> 5, lane = t & 31, o0 = w * 8;
    float acc[8];
    #pragma unroll
    for (int i = 0; i < 8; i++) acc[i] = 0.f;
    #pragma unroll
    for (int c = 0; c < C0; c++) {
        float xv = x0s[c][lane];
        float4 wa = *(const float4*)&W0s[c][o0];
        float4 wb = *(const float4*)&W0s[c][o0 + 4];
        acc[0] = fmaf(wa.x, xv, acc[0]);
        acc[1] = fmaf(wa.y, xv, acc[1]);
        acc[2] = fmaf(wa.z, xv, acc[2]);
        acc[3] = fmaf(wa.w, xv, acc[3]);
        acc[4] = fmaf(wb.x, xv, acc[4]);
        acc[5] = fmaf(wb.y, xv, acc[5]);
        acc[6] = fmaf(wb.z, xv, acc[6]);
        acc[7] = fmaf(wb.w, xv, acc[7]);
    }
    size_t base = ((size_t)b*NN + n0 + lane)*O1 + o0;
    *(float4*)&g_P[base]     = make_float4(acc[0], acc[1], acc[2], acc[3]);
    *(float4*)&g_P[base + 4] = make_float4(acc[4], acc[5], acc[6], acc[7]);
}

// ---------------- stats1: Qp per bp + BN0 stats over gathered P (no x1 materialized) ----
// block = 8 warps; warp w handles bp = blockIdx*8 + w.
// Within warp: 16 lanes per row (float4 per lane = coalesced 256B row), 2 rows per iter.
__global__ __launch_bounds__(256) void stats1(
    const float* __restrict__ xyz, const int* __restrict__ sample_idx,
    const int* __restrict__ neighbor_idx, const float* __restrict__ W0,
    const float* __restrict__ b0, float* __restrict__ out, int xyz_ofs)
{
    __shared__ float sQp[8][68];
    int t = threadIdx.x, w = t >> 5, lane = t & 31;
    int bp = blockIdx.x * 8 + w;
    int b = bp >> 10;

    // center (broadcast loads)
    int sp = sample_idx[bp];
    float c0v = xyz[((size_t)b*NN + sp)*3 + 0];
    float c1v = xyz[((size_t)b*NN + sp)*3 + 1];
    float c2v = xyz[((size_t)b*NN + sp)*3 + 2];
    if (lane < 3 && xyz_ofs > 0)
        out[bp*3 + lane] = (lane == 0) ? c0v : (lane == 1 ? c1v : c2v);

    // Qp for channels lane and lane+32
    #pragma unroll
    for (int h = 0; h < 2; h++) {
        int ch = lane + 32*h;
        const float* wr = &W0[ch*C0];
        float q = b0[ch] - (wr[0]*c0v + wr[1]*c1v + wr[2]*c2v);
        sQp[w][ch] = q;
        g_Qp[(size_t)bp*O1 + ch] = q;
    }
    __syncwarp();

    int cb = (lane & 15) << 2;                 // channel base for this lane
    float4 myQ = *(const float4*)&sQp[w][cb];
    const int* nptr = &neighbor_idx[bp*NS];

    float s0=0.f,s1=0.f,s2=0.f,s3=0.f, q0=0.f,q1=0.f,q2=0.f,q3=0.f;
    #pragma unroll 4
    for (int it = 0; it < 16; it++) {
        int sidx = it*2 + (lane >> 4);
        int nbr = nptr[sidx];
        float4 v = *(const float4*)&g_P[((size_t)b*NN + nbr)*O1 + cb];
        v.x += myQ.x; v.y += myQ.y; v.z += myQ.z; v.w += myQ.w;
        s0 += v.x; q0 += v.x*v.x;
        s1 += v.y; q1 += v.y*v.y;
        s2 += v.z; q2 += v.z*v.z;
        s3 += v.w; q3 += v.w*v.w;
    }
    s0 += __shfl_xor_sync(0xffffffffu, s0, 16);
    s1 += __shfl_xor_sync(0xffffffffu, s1, 16);
    s2 += __shfl_xor_sync(0xffffffffu, s2, 16);
    s3 += __shfl_xor_sync(0xffffffffu, s3, 16);
    q0 += __shfl_xor_sync(0xffffffffu, q0, 16);
    q1 += __shfl_xor_sync(0xffffffffu, q1, 16);
    q2 += __shfl_xor_sync(0xffffffffu, q2, 16);
    q3 += __shfl_xor_sync(0xffffffffu, q3, 16);
    if (lane < 16) {
        int slot = bp & 63;
        atomicAdd(&g_statS[(cb    )*64 + slot], s0);
        atomicAdd(&g_statS[(cb + 1)*64 + slot], s1);
        atomicAdd(&g_statS[(cb + 2)*64 + slot], s2);
        atomicAdd(&g_statS[(cb + 3)*64 + slot], s3);
        atomicAdd(&g_statQ[(cb    )*64 + slot], q0);
        atomicAdd(&g_statQ[(cb + 1)*64 + slot], q1);
        atomicAdd(&g_statQ[(cb + 2)*64 + slot], q2);
        atomicAdd(&g_statQ[(cb + 3)*64 + slot], q3);
    }
}

// ---------------- BN finalize ----------------
__global__ void bn_finalize(int layer, int O, const float* __restrict__ gamma,
                            const float* __restrict__ beta)
{
    int o = blockIdx.x * blockDim.x + threadIdx.x;
    if (o >= O) return;
    float s = 0.f, q = 0.f;
    int base = layer*256*64 + o*64;
    #pragma unroll 8
    for (int k = 0; k < 64; k++) { s += g_statS[base + k]; q += g_statQ[base + k]; }
    float invM = 1.0f / (float)MTOT;
    float mu   = s * invM;
    float var  = q * invM - mu*mu;
    float a    = gamma[o] * rsqrtf(var + BNEPS);
    g_bnA[layer*256 + o] = a;
    g_bnC[layer*256 + o] = beta[o] - a*mu;
}

// ---------------- layers 2/3: warp-MMA (mma.sync bf16, hi/lo 3-pass) ----------------
// CTA tile: 128m x 128o, K chunked by 64. 8 warps: warp = 32m x 64o.
// LAYER==2 stages X by gathering P (L2-resident) + Qp; LAYER==3 reads g_x2m.
#define SM_XH 0
#define SM_XL 18432
#define SM_WH 36864
#define SM_WL 55296
#define CONV_SMEM 73728

template <int LAYER>
__global__ __launch_bounds__(256, 2) void conv_mma(const float* __restrict__ bias,
                                                   const int* __restrict__ neighbor_idx)
{
    constexpr int C      = (LAYER == 2) ? O1 : O2;
    constexpr int NCHUNK = C / 64;
    constexpr int bnofs  = (LAYER == 2) ? 0 : 256;
    constexpr int stofs  = (LAYER == 2) ? 1*256*64 : 2*256*64;
    const unsigned* __restrict__ WhG =
        (const unsigned*)((LAYER == 2) ? (const void*)g_W1h : (const void*)g_W2h);
    const unsigned* __restrict__ WlG =
        (const unsigned*)((LAYER == 2) ? (const void*)g_W1l : (const void*)g_W2l);

    extern __shared__ __align__(16) char smc[];
    unsigned sb = smem_u32(smc);
    unsigned* Xhs = (unsigned*)(smc + SM_XH);
    unsigned* Xls = (unsigned*)(smc + SM_XL);
    unsigned* Whs = (unsigned*)(smc + SM_WH);
    unsigned* Wls = (unsigned*)(smc + SM_WL);

    int t = threadIdx.x, w = t >> 5, lane = t & 31;
    int m0 = blockIdx.x * 128;
    int o0 = blockIdx.y * 128;

    float acc[2][8][4];
    #pragma unroll
    for (int a = 0; a < 2; a++)
        #pragma unroll
        for (int b = 0; b < 8; b++)
            #pragma unroll
            for (int c = 0; c < 4; c++) acc[a][b][c] = 0.f;

    int mw = (w & 3) * 32;
    int ow = (w >> 2) * 64;
    unsigned aoff = sb + SM_XH + (unsigned)(mw + (lane & 15)) * 144u + ((lane & 16) ? 16u : 0u);
    unsigned boff = sb + SM_WH + (unsigned)(ow + ((lane >> 4) << 3) + (lane & 7)) * 144u
                    + ((lane & 8) ? 16u : 0u);

    for (int ck = 0; ck < NCHUNK; ck++) {
        int kc0 = ck * 64;
        // ---- stage X chunk: (gather P + Qp | read x2m) + BN + ReLU + hi/lo split ----
        #pragma unroll
        for (int idx = t; idx < 2048; idx += 256) {
            int row = idx >> 4, c4 = (idx & 15) << 2;
            float4 v;
            if (LAYER == 2) {
                int m  = m0 + row;
                int bp = m >> 5, sN = m & 31;
                int b  = bp >> 10;
                int nbr = neighbor_idx[bp*NS + sN];
                v = *(const float4*)&g_P[((size_t)b*NN + nbr)*O1 + c4];
                float4 Q = *(const float4*)&g_Qp[(size_t)bp*O1 + c4];
                v.x += Q.x; v.y += Q.y; v.z += Q.z; v.w += Q.w;
            } else {
                v = *(const float4*)&g_x2m[(size_t)(m0 + row)*C + kc0 + c4];
            }
            float4 A  = *(const float4*)&g_bnA[bnofs + kc0 + c4];
            float4 Cc = *(const float4*)&g_bnC[bnofs + kc0 + c4];
            float x0 = fmaxf(fmaf(A.x, v.x, Cc.x), 0.f);
            float x1 = fmaxf(fmaf(A.y, v.y, Cc.y), 0.f);
            float x2 = fmaxf(fmaf(A.z, v.z, Cc.z), 0.f);
            float x3 = fmaxf(fmaf(A.w, v.w, Cc.w), 0.f);
            __nv_bfloat16 h0,l0,h1,l1,h2,l2,h3,l3;
            split_bf16(x0,h0,l0); split_bf16(x1,h1,l1);
            split_bf16(x2,h2,l2); split_bf16(x3,h3,l3);
            uint2 hp; hp.x = bfpack(h0,h1); hp.y = bfpack(h2,h3);
            uint2 lp; lp.x = bfpack(l0,l1); lp.y = bfpack(l2,l3);
            *(uint2*)&Xhs[row*36 + (c4 >> 1)] = hp;
            *(uint2*)&Xls[row*36 + (c4 >> 1)] = lp;
        }
        // ---- stage W chunk (pre-split bf16), padded rows ----
        #pragma unroll
        for (int idx = t; idx < 1024; idx += 256) {
            int row = idx >> 3, cu = (idx & 7) << 2;
            size_t src = (size_t)(o0 + row)*(C/2) + (kc0 >> 1) + cu;
            *(uint4*)&Whs[row*36 + cu] = *(const uint4*)&WhG[src];
            *(uint4*)&Wls[row*36 + cu] = *(const uint4*)&WlG[src];
        }
        __syncthreads();

        // ---- compute: 4 k-steps of m16n8k16, hi/lo 3-pass ----
        #pragma unroll
        for (int kt = 0; kt < 4; kt++) {
            unsigned ab = aoff + kt*32;
            unsigned ah0[4], ah1[4], al0[4], al1[4];
            ldsm4(ah0, ab);
            ldsm4(ah1, ab + 16*144);
            ldsm4(al0, ab + SM_XL);
            ldsm4(al1, ab + SM_XL + 16*144);
            #pragma unroll
            for (int np = 0; np < 4; np++) {
                unsigned bb = boff + np*(16*144) + kt*32;
                unsigned bh[4], bl[4];
                ldsm4(bh, bb);
                ldsm4(bl, bb + (SM_WL - SM_WH));
                mma16816(acc[0][2*np],   ah0, bh[0], bh[1]);
                mma16816(acc[0][2*np],   ah0, bl[0], bl[1]);
                mma16816(acc[0][2*np],   al0, bh[0], bh[1]);
                mma16816(acc[1][2*np],   ah1, bh[0], bh[1]);
                mma16816(acc[1][2*np],   ah1, bl[0], bl[1]);
                mma16816(acc[1][2*np],   al1, bh[0], bh[1]);
                mma16816(acc[0][2*np+1], ah0, bh[2], bh[3]);
                mma16816(acc[0][2*np+1], ah0, bl[2], bl[3]);
                mma16816(acc[0][2*np+1], al0, bh[2], bh[3]);
                mma16816(acc[1][2*np+1], ah1, bh[2], bh[3]);
                mma16816(acc[1][2*np+1], ah1, bl[2], bl[3]);
                mma16816(acc[1][2*np+1], al1, bh[2], bh[3]);
            }
        }
        __syncthreads();
    }

    // ---- epilogue: bias, stats, store (L2) or max/min (L3) ----
    int g  = lane >> 2;
    int c2 = (lane & 3) << 1;
    int bslot = blockIdx.x & 63;
    #pragma unroll
    for (int nt = 0; nt < 8; nt++) {
        int col = o0 + ow + nt*8 + c2;
        float2 bv = *(const float2*)&bias[col];
        float v00 = acc[0][nt][0] + bv.x, v01 = acc[0][nt][1] + bv.y;
        float v10 = acc[0][nt][2] + bv.x, v11 = acc[0][nt][3] + bv.y;
        float w00 = acc[1][nt][0] + bv.x, w01 = acc[1][nt][1] + bv.y;
        float w10 = acc[1][nt][2] + bv.x, w11 = acc[1][nt][3] + bv.y;

        if (LAYER == 2) {
            int r = m0 + mw + g;
            *(float2*)&g_x2m[(size_t)(r     )*O2 + col] = make_float2(v00, v01);
            *(float2*)&g_x2m[(size_t)(r +  8)*O2 + col] = make_float2(v10, v11);
            *(float2*)&g_x2m[(size_t)(r + 16)*O2 + col] = make_float2(w00, w01);
            *(float2*)&g_x2m[(size_t)(r + 24)*O2 + col] = make_float2(w10, w11);
        }

        float s0 = rsum3(v00 + v10 + w00 + w10);
        float s1 = rsum3(v01 + v11 + w01 + w11);
        float q0 = rsum3(v00*v00 + v10*v10 + w00*w00 + w10*w10);
        float q1 = rsum3(v01*v01 + v11*v11 + w01*w01 + w11*w11);

        float mx0 = 0.f, mx1 = 0.f, mn0 = 0.f, mn1 = 0.f;
        if (LAYER == 3) {
            mx0 = rmax3(fmaxf(fmaxf(v00, v10), fmaxf(w00, w10)));
            mn0 = rmin3(fminf(fminf(v00, v10), fminf(w00, w10)));
            mx1 = rmax3(fmaxf(fmaxf(v01, v11), fmaxf(w01, w11)));
            mn1 = rmin3(fminf(fminf(v01, v11), fminf(w01, w11)));
        }
        if (lane < 4) {
            atomicAdd(&g_statS[stofs + (col    )*64 + bslot], s0);
            atomicAdd(&g_statS[stofs + (col + 1)*64 + bslot], s1);
            atomicAdd(&g_statQ[stofs + (col    )*64 + bslot], q0);
            atomicAdd(&g_statQ[stofs + (col + 1)*64 + bslot], q1);
            if (LAYER == 3) {
                int bp = (m0 + mw) >> 5;
                *(float2*)&g_xmaxT[bp*O3 + col] = make_float2(mx0, mx1);
                *(float2*)&g_xminT[bp*O3 + col] = make_float2(mn0, mn1);
            }
        }
    }
}

// ---------------- final: BN2 affine + ReLU on max/min, transpose to output ----------------
__global__ void finalize_out(float* __restrict__ out, int ofs) {
    __shared__ float tile[32][33];
    int o0  = blockIdx.y * 32;
    int bp0 = blockIdx.x * 32;
    int tx = threadIdx.x, ty = threadIdx.y;   // 32 x 8
    float a = g_bnA[512 + o0 + tx], c = g_bnC[512 + o0 + tx];
    #pragma unroll
    for (int i = 0; i < 32; i += 8) {
        int bp = bp0 + ty + i;
        float mx = g_xmaxT[bp*O3 + o0 + tx];
        float mn = g_xminT[bp*O3 + o0 + tx];
        float x = (a >= 0.f) ? mx : mn;
        tile[ty + i][tx] = fmaxf(fmaf(a, x, c), 0.f);
    }
    __syncthreads();
    int b  = bp0 >> 10;
    int p0 = bp0 & 1023;
    #pragma unroll
    for (int i = 0; i < 32; i += 8) {
        int o = o0 + ty + i;
        out[ofs + ((size_t)b*O3 + o)*NPTS + p0 + tx] = tile[tx][ty + i];
    }
}

// ---------------- launch ----------------
extern "C" void kernel_launch(void* const* d_in, const int* in_sizes, int n_in,
                              void* d_out, int out_size) {
    const float* xyz    = (const float*)d_in[0];
    const float* points = (const float*)d_in[1];
    const int*   sidx   = (const int*)  d_in[2];
    const int*   nidx   = (const int*)  d_in[3];
    const float* W0 = (const float*)d_in[4],  *b0 = (const float*)d_in[5];
    const float* g0 = (const float*)d_in[6],  *be0 = (const float*)d_in[7];
    const float* W1 = (const float*)d_in[8],  *b1 = (const float*)d_in[9];
    const float* g1 = (const float*)d_in[10], *be1 = (const float*)d_in[11];
    const float* W2 = (const float*)d_in[12], *b2 = (const float*)d_in[13];
    const float* g2 = (const float*)d_in[14], *be2 = (const float*)d_in[15];
    float* out = (float*)d_out;

    int xyz_ofs = (out_size > O3*BPTOT) ? (out_size - O3*BPTOT) : 0;

    cudaFuncSetAttribute(conv_mma<2>, cudaFuncAttributeMaxDynamicSharedMemorySize, CONV_SMEM);
    cudaFuncSetAttribute(conv_mma<3>, cudaFuncAttributeMaxDynamicSharedMemorySize, CONV_SMEM);

    zero_stats<<<(3*256*64 + 255)/256, 256>>>();
    convert_w<<<(O3*O2 + 255)/256, 256>>>(W1, W2);
    precompute_P<<<(BB*NN)/32, 256>>>(xyz, points, W0);
    stats1<<<BPTOT/8, 256>>>(xyz, sidx, nidx, W0, b0, out, xyz_ofs);
    bn_finalize<<<1, 64>>>(0, O1, g0, be0);
    conv_mma<2><<<dim3(MTOT/128, 1), 256, CONV_SMEM>>>(b1, nidx);
    bn_finalize<<<1, 128>>>(1, O2, g1, be1);
    conv_mma<3><<<dim3(MTOT/128, O3/128), 256, CONV_SMEM>>>(b2, nidx);
    bn_finalize<<<1, 256>>>(2, O3, g2, be2);
    finalize_out<<<dim3(BPTOT/32, O3/32), dim3(32, 8)>>>(out, xyz_ofs);
}